// round 2
// baseline (speedup 1.0000x reference)
#include <cuda_runtime.h>
#include <cuda_bf16.h>
#include <math.h>

// ---------------------------------------------------------------------------
// GCN_9062380994846: 3-layer GCN + mean pool + classifier + log_softmax
//  x [20000,256] f32 | edge_index [2,320000] int32-or-int64 |
//  batch [20000] int32-or-int64 (sorted) | W1..W3 [256,256], b1..b3 [256],
//  Wc [256,10], bc [10] f32.  Output: logits[64,10] ++ log_softmax[64,10].
// ---------------------------------------------------------------------------

#define N_NODES   20000
#define N_EDGES   320000
#define DIM       256
#define N_GRAPHS  64
#define N_CLASSES 10

// ---------------- scratch (device globals; no allocation allowed) ----------
__device__ float g_T[N_NODES * DIM];   // GEMM output (pre-aggregation)
__device__ float g_A[N_NODES * DIM];   // h1 / h3
__device__ float g_B[N_NODES * DIM];   // h2
__device__ int   g_src32[N_EDGES];
__device__ int   g_dst32[N_EDGES];
__device__ int   g_batch32[N_NODES];
__device__ int   g_cnt[N_NODES];       // in-degree (no self loop)
__device__ int   g_off[N_NODES + 1];   // CSR offsets
__device__ int   g_cur[N_NODES];       // CSR fill cursors
__device__ int   g_csr[N_EDGES];       // CSR src indices
__device__ float g_dinv[N_NODES];      // rsqrt(deg)
__device__ float g_pool[N_GRAPHS * DIM];
__device__ float g_gcnt[N_GRAPHS];
__device__ int   g_ei_is64;
__device__ int   g_b_is64;

// ---------------- dtype detection -------------------------------------------
// If the buffer really holds int64 node indices, every 8-byte word is in
// [0, N_NODES). If it holds int32, the 8-byte word packs two int32s and is
// >= 2^32 whenever the high int32 is nonzero — certain over 1024 samples.
__global__ void detect_kernel(const void* ei, const void* batch) {
    int t = threadIdx.x;  // 1024 threads, 1 block
    if (t == 0) { g_ei_is64 = 1; g_b_is64 = 1; }
    __syncthreads();
    long long v = ((const long long*)ei)[t];
    if (v < 0 || v >= N_NODES) atomicExch(&g_ei_is64, 0);
    long long b = ((const long long*)batch)[t];
    if (b < 0 || b >= N_GRAPHS) atomicExch(&g_b_is64, 0);
}

__global__ void convert_edges_kernel(const void* ei) {
    int e = blockIdx.x * blockDim.x + threadIdx.x;
    if (e >= N_EDGES) return;
    int s, d;
    if (g_ei_is64) {
        s = (int)((const long long*)ei)[e];
        d = (int)((const long long*)ei)[N_EDGES + e];
    } else {
        s = ((const int*)ei)[e];
        d = ((const int*)ei)[N_EDGES + e];
    }
    g_src32[e] = min(max(s, 0), N_NODES - 1);
    g_dst32[e] = min(max(d, 0), N_NODES - 1);
}

__global__ void convert_batch_kernel(const void* batch) {
    int i = blockIdx.x * blockDim.x + threadIdx.x;
    if (i >= N_NODES) return;
    int b = g_b_is64 ? (int)((const long long*)batch)[i] : ((const int*)batch)[i];
    g_batch32[i] = min(max(b, 0), N_GRAPHS - 1);
}

// ---------------- init: zero accumulators ----------------------------------
__global__ void init_kernel() {
    int i = blockIdx.x * blockDim.x + threadIdx.x;
    if (i < N_NODES) g_cnt[i] = 0;
    if (i < N_GRAPHS * DIM) g_pool[i] = 0.0f;
    if (i < N_GRAPHS) g_gcnt[i] = 0.0f;
}

// ---------------- degree count ----------------------------------------------
__global__ void count_kernel() {
    int e = blockIdx.x * blockDim.x + threadIdx.x;
    if (e < N_EDGES) atomicAdd(&g_cnt[g_dst32[e]], 1);
}

// ---------------- single-block scan: offsets + cursors + dinv ---------------
__global__ void scan_kernel() {
    __shared__ int sdata[1024];
    const int t = threadIdx.x;
    const int per = (N_NODES + 1023) / 1024;  // 20
    const int base = t * per;
    int s = 0;
    for (int j = 0; j < per; j++) {
        int idx = base + j;
        if (idx < N_NODES) s += g_cnt[idx];
    }
    sdata[t] = s;
    __syncthreads();
    for (int o = 1; o < 1024; o <<= 1) {
        int v = (t >= o) ? sdata[t - o] : 0;
        __syncthreads();
        sdata[t] += v;
        __syncthreads();
    }
    int running = sdata[t] - s;  // exclusive prefix
    for (int j = 0; j < per; j++) {
        int idx = base + j;
        if (idx < N_NODES) {
            g_off[idx] = running;
            g_cur[idx] = running;
            g_dinv[idx] = rsqrtf((float)g_cnt[idx] + 1.0f);  // +1 self loop
            running += g_cnt[idx];
        }
    }
    if (t == 1023) g_off[N_NODES] = running;
}

// ---------------- CSR fill ---------------------------------------------------
__global__ void fill_kernel() {
    int e = blockIdx.x * blockDim.x + threadIdx.x;
    if (e < N_EDGES) {
        int d = g_dst32[e];
        int p = atomicAdd(&g_cur[d], 1);
        if (p >= 0 && p < N_EDGES) g_csr[p] = g_src32[e];
    }
}

// ---------------- SGEMM: C[M,256] = A[M,256] @ B[256,256] -------------------
__global__ __launch_bounds__(256) void sgemm256(const float* __restrict__ A,
                                                const float* __restrict__ B,
                                                float* __restrict__ C, int M) {
    const int N = DIM, K = DIM;
    const int BM = 128, BN = 128, BK = 8, TM = 8, TN = 8;
    __shared__ float As[BK][BM];
    __shared__ float Bs[BK][BN];
    const int tid = threadIdx.x;
    const int rowBase = blockIdx.y * BM;
    const int colBase = blockIdx.x * BN;

    const int aRow = tid >> 1;
    const int aCol = (tid & 1) * 4;
    const int bRow = tid >> 5;
    const int bCol = (tid & 31) * 4;
    const int tRow = (tid >> 4) * TM;
    const int tCol = (tid & 15) * TN;

    float acc[TM][TN];
#pragma unroll
    for (int m = 0; m < TM; m++)
#pragma unroll
        for (int n = 0; n < TN; n++) acc[m][n] = 0.0f;

    for (int k0 = 0; k0 < K; k0 += BK) {
        int gRow = rowBase + aRow;
        float4 a4 = make_float4(0.f, 0.f, 0.f, 0.f);
        if (gRow < M)
            a4 = *reinterpret_cast<const float4*>(&A[gRow * K + k0 + aCol]);
        As[aCol + 0][aRow] = a4.x;
        As[aCol + 1][aRow] = a4.y;
        As[aCol + 2][aRow] = a4.z;
        As[aCol + 3][aRow] = a4.w;
        float4 b4 = *reinterpret_cast<const float4*>(
            &B[(k0 + bRow) * N + colBase + bCol]);
        *reinterpret_cast<float4*>(&Bs[bRow][bCol]) = b4;
        __syncthreads();

#pragma unroll
        for (int k = 0; k < BK; k++) {
            float regM[TM], regN[TN];
            float4 m0 = *reinterpret_cast<float4*>(&As[k][tRow]);
            float4 m1 = *reinterpret_cast<float4*>(&As[k][tRow + 4]);
            regM[0] = m0.x; regM[1] = m0.y; regM[2] = m0.z; regM[3] = m0.w;
            regM[4] = m1.x; regM[5] = m1.y; regM[6] = m1.z; regM[7] = m1.w;
            float4 n0 = *reinterpret_cast<float4*>(&Bs[k][tCol]);
            float4 n1 = *reinterpret_cast<float4*>(&Bs[k][tCol + 4]);
            regN[0] = n0.x; regN[1] = n0.y; regN[2] = n0.z; regN[3] = n0.w;
            regN[4] = n1.x; regN[5] = n1.y; regN[6] = n1.z; regN[7] = n1.w;
#pragma unroll
            for (int m = 0; m < TM; m++)
#pragma unroll
                for (int n = 0; n < TN; n++)
                    acc[m][n] = fmaf(regM[m], regN[n], acc[m][n]);
        }
        __syncthreads();
    }

#pragma unroll
    for (int m = 0; m < TM; m++) {
        int r = rowBase + tRow + m;
        if (r < M) {
            float4 o0 = make_float4(acc[m][0], acc[m][1], acc[m][2], acc[m][3]);
            float4 o1 = make_float4(acc[m][4], acc[m][5], acc[m][6], acc[m][7]);
            *reinterpret_cast<float4*>(&C[r * N + colBase + tCol]) = o0;
            *reinterpret_cast<float4*>(&C[r * N + colBase + tCol + 4]) = o1;
        }
    }
}

// ---------------- aggregation: out = f(A_norm @ T + b) ----------------------
// MODE 0: relu(agg + b)  | MODE 1: relu(resid + agg + b) | MODE 2: agg + b
template <int MODE>
__global__ __launch_bounds__(256) void agg_kernel(
    const float* __restrict__ T, const float* __restrict__ bias,
    const float* __restrict__ resid, float* __restrict__ out) {
    const int i = blockIdx.x;
    const int d = threadIdx.x;
    const float di = g_dinv[i];
    float acc = T[i * DIM + d] * di * di;  // self loop
    const int e0 = g_off[i], e1 = g_off[i + 1];
    __shared__ int ss[256];
    __shared__ float sw[256];
    for (int base = e0; base < e1; base += 256) {
        int c = min(256, e1 - base);
        if (d < c) {
            int s = g_csr[base + d];
            ss[d] = s;
            sw[d] = g_dinv[s] * di;
        }
        __syncthreads();
#pragma unroll 4
        for (int j = 0; j < c; j++)
            acc = fmaf(T[ss[j] * DIM + d], sw[j], acc);
        __syncthreads();
    }
    acc += bias[d];
    if (MODE == 1) acc += resid[i * DIM + d];
    if (MODE <= 1) acc = fmaxf(acc, 0.0f);
    out[i * DIM + d] = acc;
}

// ---------------- pooling ----------------------------------------------------
__global__ void gcount_kernel() {
    int i = blockIdx.x * blockDim.x + threadIdx.x;
    if (i < N_NODES) atomicAdd(&g_gcnt[g_batch32[i]], 1.0f);
}

__global__ __launch_bounds__(256) void pool_kernel(const float* __restrict__ h3) {
    const int d = threadIdx.x;
    const int r0 = blockIdx.x * 64;
    const int r1 = min(r0 + 64, N_NODES);
    if (r0 >= N_NODES) return;
    float acc = 0.0f;
    int cur = g_batch32[r0];
    for (int i = r0; i < r1; i++) {
        int g = g_batch32[i];
        if (g != cur) {
            atomicAdd(&g_pool[cur * DIM + d], acc);
            acc = 0.0f;
            cur = g;
        }
        acc += h3[i * DIM + d];
    }
    atomicAdd(&g_pool[cur * DIM + d], acc);
}

// ---------------- classifier + log_softmax ----------------------------------
__global__ __launch_bounds__(256) void cls_kernel(const float* __restrict__ Wc,
                                                  const float* __restrict__ bc,
                                                  float* __restrict__ out,
                                                  int out_size) {
    const int g = blockIdx.x;
    const int t = threadIdx.x;
    __shared__ float p[DIM];
    __shared__ float logits[N_CLASSES];
    float cnt = fmaxf(g_gcnt[g], 1.0f);
    p[t] = g_pool[g * DIM + t] / cnt;
    __syncthreads();
    const int w = t >> 5, lane = t & 31;
    for (int cls = w; cls < N_CLASSES; cls += 8) {
        float s = 0.0f;
        for (int k = lane; k < DIM; k += 32) s += p[k] * Wc[k * N_CLASSES + cls];
#pragma unroll
        for (int o = 16; o; o >>= 1) s += __shfl_xor_sync(0xffffffffu, s, o);
        if (lane == 0) logits[cls] = s + bc[cls];
    }
    __syncthreads();
    if (t < N_CLASSES) {
        float mx = -1e30f;
#pragma unroll
        for (int k = 0; k < N_CLASSES; k++) mx = fmaxf(mx, logits[k]);
        float sum = 0.0f;
#pragma unroll
        for (int k = 0; k < N_CLASSES; k++) sum += expf(logits[k] - mx);
        float lse = mx + logf(sum);
        out[g * N_CLASSES + t] = logits[t];
        if (out_size >= 2 * N_GRAPHS * N_CLASSES)
            out[N_GRAPHS * N_CLASSES + g * N_CLASSES + t] = logits[t] - lse;
    }
}

// ---------------- launch -----------------------------------------------------
extern "C" void kernel_launch(void* const* d_in, const int* in_sizes, int n_in,
                              void* d_out, int out_size) {
    const float* x = (const float*)d_in[0];
    const void*  ei = d_in[1];
    const void*  batch = d_in[2];
    const float* W1 = (const float*)d_in[3];
    const float* b1 = (const float*)d_in[4];
    const float* W2 = (const float*)d_in[5];
    const float* b2 = (const float*)d_in[6];
    const float* W3 = (const float*)d_in[7];
    const float* b3 = (const float*)d_in[8];
    const float* Wc = (const float*)d_in[9];
    const float* bc = (const float*)d_in[10];
    float* out = (float*)d_out;

    float* T; float* A; float* B;
    cudaGetSymbolAddress((void**)&T, g_T);
    cudaGetSymbolAddress((void**)&A, g_A);
    cudaGetSymbolAddress((void**)&B, g_B);

    // graph preprocessing (once per call)
    detect_kernel<<<1, 1024>>>(ei, batch);
    convert_edges_kernel<<<(N_EDGES + 255) / 256, 256>>>(ei);
    convert_batch_kernel<<<(N_NODES + 255) / 256, 256>>>(batch);
    init_kernel<<<(N_NODES + 255) / 256, 256>>>();
    count_kernel<<<(N_EDGES + 255) / 256, 256>>>();
    scan_kernel<<<1, 1024>>>();
    fill_kernel<<<(N_EDGES + 255) / 256, 256>>>();

    dim3 ggrid(DIM / 128, (N_NODES + 127) / 128);

    // layer 1: h1 = relu(agg(x@W1) + b1)
    sgemm256<<<ggrid, 256>>>(x, W1, T, N_NODES);
    agg_kernel<0><<<N_NODES, 256>>>(T, b1, nullptr, A);
    // layer 2: h2 = relu(h1 + agg(h1@W2) + b2)
    sgemm256<<<ggrid, 256>>>(A, W2, T, N_NODES);
    agg_kernel<1><<<N_NODES, 256>>>(T, b2, A, B);
    // layer 3: h3 = agg(h2@W3) + b3
    sgemm256<<<ggrid, 256>>>(B, W3, T, N_NODES);
    agg_kernel<2><<<N_NODES, 256>>>(T, b3, nullptr, A);

    // pooling + classifier
    gcount_kernel<<<(N_NODES + 255) / 256, 256>>>();
    pool_kernel<<<(N_NODES + 63) / 64, 256>>>(A);
    cls_kernel<<<N_GRAPHS, 256>>>(Wc, bc, out, out_size);
}

// round 3
// speedup vs baseline: 1.0238x; 1.0238x over previous
#include <cuda_runtime.h>
#include <cuda_bf16.h>
#include <math.h>

// ---------------------------------------------------------------------------
// GCN_9062380994846: 3-layer GCN + mean pool + classifier + log_softmax
// ---------------------------------------------------------------------------

#define N_NODES   20000
#define N_EDGES   320000
#define DIM       256
#define N_GRAPHS  64
#define N_CLASSES 10

typedef unsigned long long u64;

// ---------------- scratch ----------------------------------------------------
__device__ float g_T[N_NODES * DIM];
__device__ float g_A[N_NODES * DIM];
__device__ float g_B[N_NODES * DIM];
__device__ int   g_src32[N_EDGES];
__device__ int   g_dst32[N_EDGES];
__device__ int   g_batch32[N_NODES];
__device__ int   g_cnt[N_NODES];
__device__ int   g_off[N_NODES + 1];
__device__ int   g_cur[N_NODES];
__device__ int   g_csr[N_EDGES];
__device__ float g_dinv[N_NODES];
__device__ float g_pool[N_GRAPHS * DIM];
__device__ float g_gcnt[N_GRAPHS];
__device__ int   g_ei_is64;
__device__ int   g_b_is64;

// ---------------- f32x2 packed math helpers ---------------------------------
__device__ __forceinline__ u64 ffma2(u64 a, u64 b, u64 c) {
    u64 d;
    asm("fma.rn.f32x2 %0, %1, %2, %3;" : "=l"(d) : "l"(a), "l"(b), "l"(c));
    return d;
}
__device__ __forceinline__ u64 pack2(float x, float y) {
    u64 r;
    asm("mov.b64 %0, {%1, %2};" : "=l"(r) : "f"(x), "f"(y));
    return r;
}
__device__ __forceinline__ float2 unpack2(u64 v) {
    float2 f;
    asm("mov.b64 {%0, %1}, %2;" : "=f"(f.x), "=f"(f.y) : "l"(v));
    return f;
}

// ---------------- dtype detection -------------------------------------------
// Strided sampling within the int32-safe word range. If data is int32, packed
// pairs exceed valid index range for (almost) all samples -> flag 0.
__global__ void detect_kernel(const void* ei, const void* batch) {
    int t = threadIdx.x;  // 1024 threads, 1 block
    if (t == 0) { g_ei_is64 = 1; g_b_is64 = 1; }
    __syncthreads();
    // ei: int32 -> 320000 words of 8B; sample within [0, 320000)
    long long v = ((const long long*)ei)[(long long)t * 312];
    if (v < 0 || v >= N_NODES) atomicExch(&g_ei_is64, 0);
    // batch: int32 -> 10000 words of 8B; sample within [0, 10000)
    long long b = ((const long long*)batch)[t * 9];
    if (b < 0 || b >= N_GRAPHS) atomicExch(&g_b_is64, 0);
}

// convert + zero-init (g_cnt, g_pool, g_gcnt) fused
__global__ void convert_edges_kernel(const void* ei) {
    int e = blockIdx.x * blockDim.x + threadIdx.x;
    if (e >= N_EDGES) return;
    if (e < N_NODES) g_cnt[e] = 0;
    if (e < N_GRAPHS * DIM) g_pool[e] = 0.0f;
    if (e < N_GRAPHS) g_gcnt[e] = 0.0f;
    int s, d;
    if (g_ei_is64) {
        s = (int)((const long long*)ei)[e];
        d = (int)((const long long*)ei)[N_EDGES + e];
    } else {
        s = ((const int*)ei)[e];
        d = ((const int*)ei)[N_EDGES + e];
    }
    g_src32[e] = min(max(s, 0), N_NODES - 1);
    g_dst32[e] = min(max(d, 0), N_NODES - 1);
}

// convert batch + graph-count fused (runs after convert_edges zeroed g_gcnt)
__global__ void convert_batch_kernel(const void* batch) {
    int i = blockIdx.x * blockDim.x + threadIdx.x;
    if (i >= N_NODES) return;
    int b = g_b_is64 ? (int)((const long long*)batch)[i] : ((const int*)batch)[i];
    b = min(max(b, 0), N_GRAPHS - 1);
    g_batch32[i] = b;
    atomicAdd(&g_gcnt[b], 1.0f);
}

__global__ void count_kernel() {
    int e = blockIdx.x * blockDim.x + threadIdx.x;
    if (e < N_EDGES) atomicAdd(&g_cnt[g_dst32[e]], 1);
}

__global__ void scan_kernel() {
    __shared__ int sdata[1024];
    const int t = threadIdx.x;
    const int per = (N_NODES + 1023) / 1024;  // 20
    const int base = t * per;
    int s = 0;
    for (int j = 0; j < per; j++) {
        int idx = base + j;
        if (idx < N_NODES) s += g_cnt[idx];
    }
    sdata[t] = s;
    __syncthreads();
    for (int o = 1; o < 1024; o <<= 1) {
        int v = (t >= o) ? sdata[t - o] : 0;
        __syncthreads();
        sdata[t] += v;
        __syncthreads();
    }
    int running = sdata[t] - s;
    for (int j = 0; j < per; j++) {
        int idx = base + j;
        if (idx < N_NODES) {
            g_off[idx] = running;
            g_cur[idx] = running;
            g_dinv[idx] = rsqrtf((float)g_cnt[idx] + 1.0f);
            running += g_cnt[idx];
        }
    }
    if (t == 1023) g_off[N_NODES] = running;
}

__global__ void fill_kernel() {
    int e = blockIdx.x * blockDim.x + threadIdx.x;
    if (e < N_EDGES) {
        int d = g_dst32[e];
        int p = atomicAdd(&g_cur[d], 1);
        if (p >= 0 && p < N_EDGES) g_csr[p] = g_src32[e];
    }
}

// ---------------- SGEMM with packed f32x2 FMA --------------------------------
// C[M,256] = A[M,256] @ B[256,256], 128x128x8 tiling, TM=TN=8.
__global__ __launch_bounds__(256) void sgemm256(const float* __restrict__ A,
                                                const float* __restrict__ B,
                                                float* __restrict__ C, int M) {
    const int N = DIM, K = DIM;
    const int BM = 128, BN = 128, BK = 8, TM = 8;
    __shared__ __align__(16) float As[BK][BM];
    __shared__ __align__(16) float Bs[BK][BN];
    const int tid = threadIdx.x;
    const int rowBase = blockIdx.y * BM;
    const int colBase = blockIdx.x * BN;

    const int aRow = tid >> 1;
    const int aCol = (tid & 1) * 4;
    const int bRow = tid >> 5;
    const int bCol = (tid & 31) * 4;
    const int tRow = (tid >> 4) * TM;
    const int tCol = (tid & 15) * TM;

    u64 acc2[TM][4];  // 8 rows x 4 packed col-pairs
#pragma unroll
    for (int m = 0; m < TM; m++)
#pragma unroll
        for (int n = 0; n < 4; n++) acc2[m][n] = 0ull;

    for (int k0 = 0; k0 < K; k0 += BK) {
        int gRow = rowBase + aRow;
        float4 a4 = make_float4(0.f, 0.f, 0.f, 0.f);
        if (gRow < M)
            a4 = *reinterpret_cast<const float4*>(&A[gRow * K + k0 + aCol]);
        As[aCol + 0][aRow] = a4.x;
        As[aCol + 1][aRow] = a4.y;
        As[aCol + 2][aRow] = a4.z;
        As[aCol + 3][aRow] = a4.w;
        float4 b4 = *reinterpret_cast<const float4*>(
            &B[(k0 + bRow) * N + colBase + bCol]);
        *reinterpret_cast<float4*>(&Bs[bRow][bCol]) = b4;
        __syncthreads();

#pragma unroll
        for (int k = 0; k < BK; k++) {
            float4 m0 = *reinterpret_cast<float4*>(&As[k][tRow]);
            float4 m1 = *reinterpret_cast<float4*>(&As[k][tRow + 4]);
            u64 md[TM];
            md[0] = pack2(m0.x, m0.x); md[1] = pack2(m0.y, m0.y);
            md[2] = pack2(m0.z, m0.z); md[3] = pack2(m0.w, m0.w);
            md[4] = pack2(m1.x, m1.x); md[5] = pack2(m1.y, m1.y);
            md[6] = pack2(m1.z, m1.z); md[7] = pack2(m1.w, m1.w);
            const u64* bn = reinterpret_cast<const u64*>(&Bs[k][tCol]);
            u64 b0 = bn[0], b1 = bn[1], b2 = bn[2], b3 = bn[3];
#pragma unroll
            for (int m = 0; m < TM; m++) {
                acc2[m][0] = ffma2(md[m], b0, acc2[m][0]);
                acc2[m][1] = ffma2(md[m], b1, acc2[m][1]);
                acc2[m][2] = ffma2(md[m], b2, acc2[m][2]);
                acc2[m][3] = ffma2(md[m], b3, acc2[m][3]);
            }
        }
        __syncthreads();
    }

#pragma unroll
    for (int m = 0; m < TM; m++) {
        int r = rowBase + tRow + m;
        if (r < M) {
            float2 p0 = unpack2(acc2[m][0]);
            float2 p1 = unpack2(acc2[m][1]);
            float2 p2 = unpack2(acc2[m][2]);
            float2 p3 = unpack2(acc2[m][3]);
            float4 o0 = make_float4(p0.x, p0.y, p1.x, p1.y);
            float4 o1 = make_float4(p2.x, p2.y, p3.x, p3.y);
            *reinterpret_cast<float4*>(&C[r * N + colBase + tCol]) = o0;
            *reinterpret_cast<float4*>(&C[r * N + colBase + tCol + 4]) = o1;
        }
    }
}

// ---------------- aggregation: out = f(A_norm @ T + b) ----------------------
// MODE 0: relu(agg + b)  | MODE 1: relu(resid + agg + b) | MODE 2: agg + b
template <int MODE>
__global__ __launch_bounds__(256) void agg_kernel(
    const float* __restrict__ T, const float* __restrict__ bias,
    const float* __restrict__ resid, float* __restrict__ out) {
    const int i = blockIdx.x;
    const int d = threadIdx.x;
    const float di = g_dinv[i];
    float acc0 = T[i * DIM + d] * di * di;  // self loop
    float acc1 = 0.0f;
    const int e0 = g_off[i], e1 = g_off[i + 1];
    __shared__ int ss[256];
    __shared__ float sw[256];
    for (int base = e0; base < e1; base += 256) {
        int c = min(256, e1 - base);
        if (d < c) {
            int s = g_csr[base + d];
            ss[d] = s;
            sw[d] = g_dinv[s] * di;
        }
        __syncthreads();
        int j = 0;
#pragma unroll 2
        for (; j + 1 < c; j += 2) {
            acc0 = fmaf(T[ss[j] * DIM + d], sw[j], acc0);
            acc1 = fmaf(T[ss[j + 1] * DIM + d], sw[j + 1], acc1);
        }
        if (j < c) acc0 = fmaf(T[ss[j] * DIM + d], sw[j], acc0);
        __syncthreads();
    }
    float acc = acc0 + acc1 + bias[d];
    if (MODE == 1) acc += resid[i * DIM + d];
    if (MODE <= 1) acc = fmaxf(acc, 0.0f);
    out[i * DIM + d] = acc;
}

// ---------------- pooling ----------------------------------------------------
__global__ __launch_bounds__(256) void pool_kernel(const float* __restrict__ h3) {
    const int d = threadIdx.x;
    const int r0 = blockIdx.x * 64;
    const int r1 = min(r0 + 64, N_NODES);
    if (r0 >= N_NODES) return;
    float acc = 0.0f;
    int cur = g_batch32[r0];
    for (int i = r0; i < r1; i++) {
        int g = g_batch32[i];
        if (g != cur) {
            atomicAdd(&g_pool[cur * DIM + d], acc);
            acc = 0.0f;
            cur = g;
        }
        acc += h3[i * DIM + d];
    }
    atomicAdd(&g_pool[cur * DIM + d], acc);
}

// ---------------- classifier + log_softmax ----------------------------------
__global__ __launch_bounds__(256) void cls_kernel(const float* __restrict__ Wc,
                                                  const float* __restrict__ bc,
                                                  float* __restrict__ out,
                                                  int out_size) {
    const int g = blockIdx.x;
    const int t = threadIdx.x;
    __shared__ float p[DIM];
    __shared__ float logits[N_CLASSES];
    float cnt = fmaxf(g_gcnt[g], 1.0f);
    p[t] = g_pool[g * DIM + t] / cnt;
    __syncthreads();
    const int w = t >> 5, lane = t & 31;
    for (int cls = w; cls < N_CLASSES; cls += 8) {
        float s = 0.0f;
        for (int k = lane; k < DIM; k += 32) s += p[k] * Wc[k * N_CLASSES + cls];
#pragma unroll
        for (int o = 16; o; o >>= 1) s += __shfl_xor_sync(0xffffffffu, s, o);
        if (lane == 0) logits[cls] = s + bc[cls];
    }
    __syncthreads();
    if (t < N_CLASSES) {
        float mx = -1e30f;
#pragma unroll
        for (int k = 0; k < N_CLASSES; k++) mx = fmaxf(mx, logits[k]);
        float sum = 0.0f;
#pragma unroll
        for (int k = 0; k < N_CLASSES; k++) sum += expf(logits[k] - mx);
        float lse = mx + logf(sum);
        out[g * N_CLASSES + t] = logits[t];
        if (out_size >= 2 * N_GRAPHS * N_CLASSES)
            out[N_GRAPHS * N_CLASSES + g * N_CLASSES + t] = logits[t] - lse;
    }
}

// ---------------- launch -----------------------------------------------------
extern "C" void kernel_launch(void* const* d_in, const int* in_sizes, int n_in,
                              void* d_out, int out_size) {
    const float* x = (const float*)d_in[0];
    const void*  ei = d_in[1];
    const void*  batch = d_in[2];
    const float* W1 = (const float*)d_in[3];
    const float* b1 = (const float*)d_in[4];
    const float* W2 = (const float*)d_in[5];
    const float* b2 = (const float*)d_in[6];
    const float* W3 = (const float*)d_in[7];
    const float* b3 = (const float*)d_in[8];
    const float* Wc = (const float*)d_in[9];
    const float* bc = (const float*)d_in[10];
    float* out = (float*)d_out;

    float* T; float* A; float* B;
    cudaGetSymbolAddress((void**)&T, g_T);
    cudaGetSymbolAddress((void**)&A, g_A);
    cudaGetSymbolAddress((void**)&B, g_B);

    detect_kernel<<<1, 1024>>>(ei, batch);
    convert_edges_kernel<<<(N_EDGES + 255) / 256, 256>>>(ei);
    convert_batch_kernel<<<(N_NODES + 255) / 256, 256>>>(batch);
    count_kernel<<<(N_EDGES + 255) / 256, 256>>>();
    scan_kernel<<<1, 1024>>>();
    fill_kernel<<<(N_EDGES + 255) / 256, 256>>>();

    dim3 ggrid(DIM / 128, (N_NODES + 127) / 128);

    sgemm256<<<ggrid, 256>>>(x, W1, T, N_NODES);
    agg_kernel<0><<<N_NODES, 256>>>(T, b1, nullptr, A);
    sgemm256<<<ggrid, 256>>>(A, W2, T, N_NODES);
    agg_kernel<1><<<N_NODES, 256>>>(T, b2, A, B);
    sgemm256<<<ggrid, 256>>>(B, W3, T, N_NODES);
    agg_kernel<2><<<N_NODES, 256>>>(T, b3, nullptr, A);

    pool_kernel<<<(N_NODES + 63) / 64, 256>>>(A);
    cls_kernel<<<N_GRAPHS, 256>>>(Wc, bc, out, out_size);
}

// round 4
// speedup vs baseline: 1.2217x; 1.1933x over previous
#include <cuda_runtime.h>
#include <cuda_bf16.h>
#include <math.h>

// ---------------------------------------------------------------------------
// GCN_9062380994846: 3-layer GCN + mean pool + classifier + log_softmax
// ---------------------------------------------------------------------------

#define N_NODES   20000
#define N_EDGES   320000
#define DIM       256
#define N_GRAPHS  64
#define N_CLASSES 10

typedef unsigned long long u64;

// ---------------- scratch ----------------------------------------------------
__device__ float g_T[N_NODES * DIM];
__device__ float g_A[N_NODES * DIM];
__device__ float g_B[N_NODES * DIM];
__device__ int   g_src32[N_EDGES];
__device__ int   g_dst32[N_EDGES];
__device__ int   g_cnt[N_NODES];
__device__ int   g_off[N_NODES + 1];
__device__ int   g_cur[N_NODES];
__device__ int   g_csr[N_EDGES];
__device__ float g_w[N_EDGES];          // dinv[src]*dinv[dst] per CSR slot
__device__ float g_dinv[N_NODES];
__device__ int   g_gstart[N_GRAPHS + 1];
__device__ float g_pool[N_GRAPHS * DIM];
__device__ int   g_ei_is64;
__device__ int   g_b_is64;

// ---------------- f32x2 helpers ----------------------------------------------
__device__ __forceinline__ u64 ffma2(u64 a, u64 b, u64 c) {
    u64 d;
    asm("fma.rn.f32x2 %0, %1, %2, %3;" : "=l"(d) : "l"(a), "l"(b), "l"(c));
    return d;
}
__device__ __forceinline__ u64 pack2(float x, float y) {
    u64 r;
    asm("mov.b64 %0, {%1, %2};" : "=l"(r) : "f"(x), "f"(y));
    return r;
}
__device__ __forceinline__ float2 unpack2(u64 v) {
    float2 f;
    asm("mov.b64 {%0, %1}, %2;" : "=f"(f.x), "=f"(f.y) : "l"(v));
    return f;
}

// ---------------- init + dtype detection --------------------------------------
__global__ void detect_kernel(const void* ei, const void* batch) {
    int t = threadIdx.x;  // 1024 threads, 1 block
    if (t == 0) { g_ei_is64 = 1; g_b_is64 = 1; }
    // zero/seed accumulators
    for (int i = t; i < N_NODES; i += 1024) g_cnt[i] = 0;
    for (int i = t; i < N_GRAPHS + 1; i += 1024) g_gstart[i] = N_NODES;
    __syncthreads();
    long long v = ((const long long*)ei)[(long long)t * 312];
    if (v < 0 || v >= N_NODES) atomicExch(&g_ei_is64, 0);
    long long b = ((const long long*)batch)[t * 9];
    if (b < 0 || b >= N_GRAPHS) atomicExch(&g_b_is64, 0);
}

// convert edges + degree count
__global__ void convert_edges_kernel(const void* ei) {
    int e = blockIdx.x * blockDim.x + threadIdx.x;
    if (e >= N_EDGES) return;
    int s, d;
    if (g_ei_is64) {
        s = (int)((const long long*)ei)[e];
        d = (int)((const long long*)ei)[N_EDGES + e];
    } else {
        s = ((const int*)ei)[e];
        d = ((const int*)ei)[N_EDGES + e];
    }
    s = min(max(s, 0), N_NODES - 1);
    d = min(max(d, 0), N_NODES - 1);
    g_src32[e] = s;
    g_dst32[e] = d;
    atomicAdd(&g_cnt[d], 1);
}

// convert batch + graph start via atomicMin (batch sorted)
__global__ void convert_batch_kernel(const void* batch) {
    int i = blockIdx.x * blockDim.x + threadIdx.x;
    if (i >= N_NODES) return;
    int b = g_b_is64 ? (int)((const long long*)batch)[i] : ((const int*)batch)[i];
    b = min(max(b, 0), N_GRAPHS - 1);
    atomicMin(&g_gstart[b], i);
}

__global__ void scan_kernel() {
    __shared__ int sdata[1024];
    const int t = threadIdx.x;
    const int per = (N_NODES + 1023) / 1024;  // 20
    const int base = t * per;
    int s = 0;
    for (int j = 0; j < per; j++) {
        int idx = base + j;
        if (idx < N_NODES) s += g_cnt[idx];
    }
    sdata[t] = s;
    __syncthreads();
    for (int o = 1; o < 1024; o <<= 1) {
        int v = (t >= o) ? sdata[t - o] : 0;
        __syncthreads();
        sdata[t] += v;
        __syncthreads();
    }
    int running = sdata[t] - s;
    for (int j = 0; j < per; j++) {
        int idx = base + j;
        if (idx < N_NODES) {
            g_off[idx] = running;
            g_cur[idx] = running;
            g_dinv[idx] = rsqrtf((float)g_cnt[idx] + 1.0f);
            running += g_cnt[idx];
        }
    }
    if (t == 1023) g_off[N_NODES] = running;
    if (t == 0) {
        // suffix-min fixup for empty graphs
        g_gstart[N_GRAPHS] = N_NODES;
        for (int g = N_GRAPHS - 1; g >= 0; g--)
            g_gstart[g] = min(g_gstart[g], g_gstart[g + 1]);
    }
}

// CSR fill + edge weight (dinv ready after scan)
__global__ void fill_kernel() {
    int e = blockIdx.x * blockDim.x + threadIdx.x;
    if (e < N_EDGES) {
        int s = g_src32[e];
        int d = g_dst32[e];
        int p = atomicAdd(&g_cur[d], 1);
        if (p >= 0 && p < N_EDGES) {
            g_csr[p] = s;
            g_w[p] = g_dinv[s] * g_dinv[d];
        }
    }
}

// ---------------- SGEMM 64x64x8, double-buffered, f32x2 FMA -------------------
// C[M,256] = A[M,256] @ B[256,256]
__global__ __launch_bounds__(256) void sgemm64(const float* __restrict__ A,
                                               const float* __restrict__ B,
                                               float* __restrict__ C, int M) {
    const int K = DIM, N = DIM, BM = 64, BN = 64, BK = 8;
    __shared__ __align__(16) float As[2][BK][BM];
    __shared__ __align__(16) float Bs[2][BK][BN];
    const int tid = threadIdx.x;
    const int rowBase = blockIdx.y * BM;
    const int colBase = blockIdx.x * BN;

    const bool loadA = tid < 128;
    const int aRow = tid >> 1;          // 0..63 (when loadA)
    const int aCol = (tid & 1) * 4;     // 0 or 4
    const int bIdx = tid - 128;
    const int bRow = bIdx >> 4;         // 0..7
    const int bCol = (bIdx & 15) * 4;   // 0..60
    const int tRow = (tid >> 4) * 4;    // 0..60
    const int tCol = (tid & 15) * 4;    // 0..60

    u64 acc[4][2];
#pragma unroll
    for (int m = 0; m < 4; m++) { acc[m][0] = 0ull; acc[m][1] = 0ull; }

    float4 pa = make_float4(0.f, 0.f, 0.f, 0.f);
    float4 pb = pa;
    if (loadA) {
        int r = rowBase + aRow;
        if (r < M) pa = *reinterpret_cast<const float4*>(&A[r * K + aCol]);
    } else {
        pb = *reinterpret_cast<const float4*>(&B[bRow * N + colBase + bCol]);
    }
    if (loadA) {
        As[0][aCol + 0][aRow] = pa.x;
        As[0][aCol + 1][aRow] = pa.y;
        As[0][aCol + 2][aRow] = pa.z;
        As[0][aCol + 3][aRow] = pa.w;
    } else {
        *reinterpret_cast<float4*>(&Bs[0][bRow][bCol]) = pb;
    }
    __syncthreads();

    int cur = 0;
    for (int k0 = 0; k0 < K; k0 += BK) {
        const bool more = (k0 + BK) < K;
        if (more) {
            if (loadA) {
                int r = rowBase + aRow;
                pa = make_float4(0.f, 0.f, 0.f, 0.f);
                if (r < M)
                    pa = *reinterpret_cast<const float4*>(&A[r * K + k0 + BK + aCol]);
            } else {
                pb = *reinterpret_cast<const float4*>(
                    &B[(k0 + BK + bRow) * N + colBase + bCol]);
            }
        }
#pragma unroll
        for (int k = 0; k < BK; k++) {
            float4 a4 = *reinterpret_cast<float4*>(&As[cur][k][tRow]);
            u64 b0 = *reinterpret_cast<u64*>(&Bs[cur][k][tCol]);
            u64 b1 = *reinterpret_cast<u64*>(&Bs[cur][k][tCol + 2]);
            u64 m0 = pack2(a4.x, a4.x);
            u64 m1 = pack2(a4.y, a4.y);
            u64 m2 = pack2(a4.z, a4.z);
            u64 m3 = pack2(a4.w, a4.w);
            acc[0][0] = ffma2(m0, b0, acc[0][0]);
            acc[0][1] = ffma2(m0, b1, acc[0][1]);
            acc[1][0] = ffma2(m1, b0, acc[1][0]);
            acc[1][1] = ffma2(m1, b1, acc[1][1]);
            acc[2][0] = ffma2(m2, b0, acc[2][0]);
            acc[2][1] = ffma2(m2, b1, acc[2][1]);
            acc[3][0] = ffma2(m3, b0, acc[3][0]);
            acc[3][1] = ffma2(m3, b1, acc[3][1]);
        }
        if (more) {
            if (loadA) {
                As[cur ^ 1][aCol + 0][aRow] = pa.x;
                As[cur ^ 1][aCol + 1][aRow] = pa.y;
                As[cur ^ 1][aCol + 2][aRow] = pa.z;
                As[cur ^ 1][aCol + 3][aRow] = pa.w;
            } else {
                *reinterpret_cast<float4*>(&Bs[cur ^ 1][bRow][bCol]) = pb;
            }
        }
        __syncthreads();
        cur ^= 1;
    }

#pragma unroll
    for (int m = 0; m < 4; m++) {
        int r = rowBase + tRow + m;
        if (r < M) {
            float2 p0 = unpack2(acc[m][0]);
            float2 p1 = unpack2(acc[m][1]);
            float4 o = make_float4(p0.x, p0.y, p1.x, p1.y);
            *reinterpret_cast<float4*>(&C[r * N + colBase + tCol]) = o;
        }
    }
}

// ---------------- aggregation ------------------------------------------------
// MODE 0: relu(agg + b) | MODE 1: relu(resid + agg + b) | MODE 2: agg + b
// 256 threads: 64 dim-lanes (float4) x 4 edge groups.
template <int MODE>
__global__ __launch_bounds__(256) void agg_kernel(
    const float4* __restrict__ T4, const float4* __restrict__ bias4,
    const float4* __restrict__ resid4, float4* __restrict__ out4) {
    const int i = blockIdx.x;
    const int tid = threadIdx.x;
    const int d4 = tid & 63;
    const int eg = tid >> 6;
    const int e0 = g_off[i], e1 = g_off[i + 1];

    float4 a0 = make_float4(0.f, 0.f, 0.f, 0.f);
    float4 a1 = a0;
    int e = e0 + eg;
    for (; e + 4 < e1; e += 8) {
        int s0 = g_csr[e];
        float w0 = g_w[e];
        int s1 = g_csr[e + 4];
        float w1 = g_w[e + 4];
        float4 v0 = T4[s0 * 64 + d4];
        float4 v1 = T4[s1 * 64 + d4];
        a0.x = fmaf(w0, v0.x, a0.x); a0.y = fmaf(w0, v0.y, a0.y);
        a0.z = fmaf(w0, v0.z, a0.z); a0.w = fmaf(w0, v0.w, a0.w);
        a1.x = fmaf(w1, v1.x, a1.x); a1.y = fmaf(w1, v1.y, a1.y);
        a1.z = fmaf(w1, v1.z, a1.z); a1.w = fmaf(w1, v1.w, a1.w);
    }
    if (e < e1) {
        int s = g_csr[e];
        float w = g_w[e];
        float4 v = T4[s * 64 + d4];
        a0.x = fmaf(w, v.x, a0.x); a0.y = fmaf(w, v.y, a0.y);
        a0.z = fmaf(w, v.z, a0.z); a0.w = fmaf(w, v.w, a0.w);
    }
    a0.x += a1.x; a0.y += a1.y; a0.z += a1.z; a0.w += a1.w;

    __shared__ float4 part[3][64];
    if (eg > 0) part[eg - 1][d4] = a0;
    __syncthreads();
    if (eg == 0) {
        const float di = g_dinv[i];
        float4 self = T4[i * 64 + d4];
        float dii = di * di;
        float4 b = bias4[d4];
        float4 acc;
        acc.x = a0.x + part[0][d4].x + part[1][d4].x + part[2][d4].x + self.x * dii + b.x;
        acc.y = a0.y + part[0][d4].y + part[1][d4].y + part[2][d4].y + self.y * dii + b.y;
        acc.z = a0.z + part[0][d4].z + part[1][d4].z + part[2][d4].z + self.z * dii + b.z;
        acc.w = a0.w + part[0][d4].w + part[1][d4].w + part[2][d4].w + self.w * dii + b.w;
        if (MODE == 1) {
            float4 r = resid4[i * 64 + d4];
            acc.x += r.x; acc.y += r.y; acc.z += r.z; acc.w += r.w;
        }
        if (MODE <= 1) {
            acc.x = fmaxf(acc.x, 0.f); acc.y = fmaxf(acc.y, 0.f);
            acc.z = fmaxf(acc.z, 0.f); acc.w = fmaxf(acc.w, 0.f);
        }
        out4[i * 64 + d4] = acc;
    }
}

// ---------------- pooling: one block per graph, writes the MEAN --------------
__global__ __launch_bounds__(256) void pool_kernel(const float4* __restrict__ h4) {
    const int g = blockIdx.x;
    const int tid = threadIdx.x;
    const int d4 = tid & 63;
    const int rg = tid >> 6;
    const int r0 = g_gstart[g], r1 = g_gstart[g + 1];
    float4 acc = make_float4(0.f, 0.f, 0.f, 0.f);
    for (int i = r0 + rg; i < r1; i += 4) {
        float4 v = h4[i * 64 + d4];
        acc.x += v.x; acc.y += v.y; acc.z += v.z; acc.w += v.w;
    }
    __shared__ float4 part[4][64];
    part[rg][d4] = acc;
    __syncthreads();
    if (rg == 0) {
        float inv = 1.0f / fmaxf((float)(r1 - r0), 1.0f);
        float4 s;
        s.x = (part[0][d4].x + part[1][d4].x + part[2][d4].x + part[3][d4].x) * inv;
        s.y = (part[0][d4].y + part[1][d4].y + part[2][d4].y + part[3][d4].y) * inv;
        s.z = (part[0][d4].z + part[1][d4].z + part[2][d4].z + part[3][d4].z) * inv;
        s.w = (part[0][d4].w + part[1][d4].w + part[2][d4].w + part[3][d4].w) * inv;
        reinterpret_cast<float4*>(g_pool)[g * 64 + d4] = s;
    }
}

// ---------------- classifier + log_softmax ------------------------------------
__global__ __launch_bounds__(256) void cls_kernel(const float* __restrict__ Wc,
                                                  const float* __restrict__ bc,
                                                  float* __restrict__ out,
                                                  int out_size) {
    const int g = blockIdx.x;
    const int t = threadIdx.x;
    __shared__ float p[DIM];
    __shared__ float logits[N_CLASSES];
    p[t] = g_pool[g * DIM + t];  // already the mean
    __syncthreads();
    const int w = t >> 5, lane = t & 31;
    for (int cls = w; cls < N_CLASSES; cls += 8) {
        float s = 0.0f;
        for (int k = lane; k < DIM; k += 32) s += p[k] * Wc[k * N_CLASSES + cls];
#pragma unroll
        for (int o = 16; o; o >>= 1) s += __shfl_xor_sync(0xffffffffu, s, o);
        if (lane == 0) logits[cls] = s + bc[cls];
    }
    __syncthreads();
    if (t < N_CLASSES) {
        float mx = -1e30f;
#pragma unroll
        for (int k = 0; k < N_CLASSES; k++) mx = fmaxf(mx, logits[k]);
        float sum = 0.0f;
#pragma unroll
        for (int k = 0; k < N_CLASSES; k++) sum += expf(logits[k] - mx);
        float lse = mx + logf(sum);
        out[g * N_CLASSES + t] = logits[t];
        if (out_size >= 2 * N_GRAPHS * N_CLASSES)
            out[N_GRAPHS * N_CLASSES + g * N_CLASSES + t] = logits[t] - lse;
    }
}

// ---------------- launch -------------------------------------------------------
extern "C" void kernel_launch(void* const* d_in, const int* in_sizes, int n_in,
                              void* d_out, int out_size) {
    const float* x = (const float*)d_in[0];
    const void*  ei = d_in[1];
    const void*  batch = d_in[2];
    const float* W1 = (const float*)d_in[3];
    const float* b1 = (const float*)d_in[4];
    const float* W2 = (const float*)d_in[5];
    const float* b2 = (const float*)d_in[6];
    const float* W3 = (const float*)d_in[7];
    const float* b3 = (const float*)d_in[8];
    const float* Wc = (const float*)d_in[9];
    const float* bc = (const float*)d_in[10];
    float* out = (float*)d_out;

    float* T; float* A; float* B;
    cudaGetSymbolAddress((void**)&T, g_T);
    cudaGetSymbolAddress((void**)&A, g_A);
    cudaGetSymbolAddress((void**)&B, g_B);

    detect_kernel<<<1, 1024>>>(ei, batch);
    convert_edges_kernel<<<(N_EDGES + 255) / 256, 256>>>(ei);
    convert_batch_kernel<<<(N_NODES + 255) / 256, 256>>>(batch);
    scan_kernel<<<1, 1024>>>();
    fill_kernel<<<(N_EDGES + 255) / 256, 256>>>();

    dim3 ggrid(DIM / 64, (N_NODES + 63) / 64);

    sgemm64<<<ggrid, 256>>>(x, W1, T, N_NODES);
    agg_kernel<0><<<N_NODES, 256>>>((const float4*)T, (const float4*)b1, nullptr,
                                    (float4*)A);
    sgemm64<<<ggrid, 256>>>(A, W2, T, N_NODES);
    agg_kernel<1><<<N_NODES, 256>>>((const float4*)T, (const float4*)b2,
                                    (const float4*)A, (float4*)B);
    sgemm64<<<ggrid, 256>>>(B, W3, T, N_NODES);
    agg_kernel<2><<<N_NODES, 256>>>((const float4*)T, (const float4*)b3, nullptr,
                                    (float4*)A);

    pool_kernel<<<N_GRAPHS, 256>>>((const float4*)A);
    cls_kernel<<<N_GRAPHS, 256>>>(Wc, bc, out, out_size);
}

// round 5
// speedup vs baseline: 1.3351x; 1.0929x over previous
#include <cuda_runtime.h>
#include <cuda_bf16.h>
#include <math.h>

// ---------------------------------------------------------------------------
// GCN_9062380994846: 3-layer GCN + mean pool + classifier + log_softmax
// ---------------------------------------------------------------------------

#define N_NODES   20000
#define N_EDGES   320000
#define DIM       256
#define N_GRAPHS  64
#define N_CLASSES 10
#define SCAN_BLK  256
#define N_SCANB   ((N_NODES + SCAN_BLK - 1) / SCAN_BLK)   // 79

typedef unsigned long long u64;

// ---------------- scratch ----------------------------------------------------
__device__ float g_T[N_NODES * DIM];
__device__ float g_A[N_NODES * DIM];
__device__ float g_B[N_NODES * DIM];
__device__ int   g_src32[N_EDGES];
__device__ int   g_dst32[N_EDGES];
__device__ int   g_cnt[N_NODES];
__device__ int   g_off[N_NODES + 1];
__device__ int   g_cur[N_NODES];
__device__ int   g_csr[N_EDGES];
__device__ float g_w[N_EDGES];
__device__ float g_dinv[N_NODES];
__device__ int   g_bsum[N_SCANB];
__device__ int   g_bbase[N_SCANB];
__device__ int   g_gstart[N_GRAPHS + 1];
__device__ float g_pool[N_GRAPHS * DIM];
__device__ int   g_ei_is64;
__device__ int   g_b_is64;

// ---------------- f32x2 helpers ----------------------------------------------
__device__ __forceinline__ u64 ffma2(u64 a, u64 b, u64 c) {
    u64 d;
    asm("fma.rn.f32x2 %0, %1, %2, %3;" : "=l"(d) : "l"(a), "l"(b), "l"(c));
    return d;
}
__device__ __forceinline__ u64 pack2(float x, float y) {
    u64 r;
    asm("mov.b64 %0, {%1, %2};" : "=l"(r) : "f"(x), "f"(y));
    return r;
}
__device__ __forceinline__ float2 unpack2(u64 v) {
    float2 f;
    asm("mov.b64 {%0, %1}, %2;" : "=f"(f.x), "=f"(f.y) : "l"(v));
    return f;
}

// ---------------- dtype detection (sampling only) -----------------------------
__global__ void detect_kernel(const void* ei, const void* batch) {
    int t = threadIdx.x;  // 1024 threads
    if (t == 0) { g_ei_is64 = 1; g_b_is64 = 1; }
    __syncthreads();
    long long v = ((const long long*)ei)[(long long)t * 312];
    if (v < 0 || v >= N_NODES) atomicExch(&g_ei_is64, 0);
    long long b = ((const long long*)batch)[t * 9];
    if (b < 0 || b >= N_GRAPHS) atomicExch(&g_b_is64, 0);
}

// convert batch + zero g_cnt + seed g_gstart (runs BEFORE convert_edges)
__global__ void convert_batch_kernel(const void* batch) {
    int i = blockIdx.x * blockDim.x + threadIdx.x;
    if (i >= N_NODES) return;
    g_cnt[i] = 0;
    if (i <= N_GRAPHS) g_gstart[i] = N_NODES;
    int b = g_b_is64 ? (int)((const long long*)batch)[i] : ((const int*)batch)[i];
    b = min(max(b, 0), N_GRAPHS - 1);
    atomicMin(&g_gstart[b], i);
}

// convert edges + degree count
__global__ void convert_edges_kernel(const void* ei) {
    int e = blockIdx.x * blockDim.x + threadIdx.x;
    if (e >= N_EDGES) return;
    int s, d;
    if (g_ei_is64) {
        s = (int)((const long long*)ei)[e];
        d = (int)((const long long*)ei)[N_EDGES + e];
    } else {
        s = ((const int*)ei)[e];
        d = ((const int*)ei)[N_EDGES + e];
    }
    s = min(max(s, 0), N_NODES - 1);
    d = min(max(d, 0), N_NODES - 1);
    g_src32[e] = s;
    g_dst32[e] = d;
    atomicAdd(&g_cnt[d], 1);
}

// ---------------- 3-phase scan -------------------------------------------------
// phase 1: per-block sums of g_cnt
__global__ __launch_bounds__(SCAN_BLK) void scan_pre() {
    const int t = threadIdx.x;
    int i = blockIdx.x * SCAN_BLK + t;
    int v = (i < N_NODES) ? g_cnt[i] : 0;
    // warp reduce
#pragma unroll
    for (int o = 16; o; o >>= 1) v += __shfl_xor_sync(0xffffffffu, v, o);
    __shared__ int ws[8];
    if ((t & 31) == 0) ws[t >> 5] = v;
    __syncthreads();
    if (t < 8) {
        int s = ws[t];
#pragma unroll
        for (int o = 4; o; o >>= 1) s += __shfl_xor_sync(0xffu, s, o);
        if (t == 0) g_bsum[blockIdx.x] = s;
    }
}

// phase 2: scan 79 block sums + suffix-min g_gstart (tiny)
__global__ void scan_mid() {
    const int t = threadIdx.x;  // 128 threads
    __shared__ int s[128];
    int v = (t < N_SCANB) ? g_bsum[t] : 0;
    s[t] = v;
    __syncthreads();
    for (int o = 1; o < 128; o <<= 1) {
        int u = (t >= o) ? s[t - o] : 0;
        __syncthreads();
        s[t] += u;
        __syncthreads();
    }
    if (t < N_SCANB) g_bbase[t] = s[t] - v;  // exclusive base
    if (t == 0) g_off[N_NODES] = s[N_SCANB - 1];
    // suffix-min fixup for empty graphs (65 values, serial is fine)
    if (t == 64) {
        g_gstart[N_GRAPHS] = N_NODES;
        for (int g = N_GRAPHS - 1; g >= 0; g--)
            g_gstart[g] = min(g_gstart[g], g_gstart[g + 1]);
    }
}

// phase 3: intra-block exclusive scan + base; write off/cur/dinv
__global__ __launch_bounds__(SCAN_BLK) void scan_post() {
    const int t = threadIdx.x;
    int i = blockIdx.x * SCAN_BLK + t;
    int c = (i < N_NODES) ? g_cnt[i] : 0;
    // inclusive warp scan
    int v = c;
#pragma unroll
    for (int o = 1; o < 32; o <<= 1) {
        int u = __shfl_up_sync(0xffffffffu, v, o);
        if ((t & 31) >= o) v += u;
    }
    __shared__ int ws[8];
    if ((t & 31) == 31) ws[t >> 5] = v;
    __syncthreads();
    if (t < 8) {
        int s = ws[t];
#pragma unroll
        for (int o = 1; o < 8; o <<= 1) {
            int u = __shfl_up_sync(0xffu, s, o);
            if (t >= o) s += u;
        }
        ws[t] = s;
    }
    __syncthreads();
    int warpBase = (t >= 32) ? ws[(t >> 5) - 1] : 0;
    int excl = g_bbase[blockIdx.x] + warpBase + v - c;
    if (i < N_NODES) {
        g_off[i] = excl;
        g_cur[i] = excl;
        g_dinv[i] = rsqrtf((float)c + 1.0f);
    }
}

// CSR fill + edge weight
__global__ void fill_kernel() {
    int e = blockIdx.x * blockDim.x + threadIdx.x;
    if (e < N_EDGES) {
        int s = g_src32[e];
        int d = g_dst32[e];
        int p = atomicAdd(&g_cur[d], 1);
        if (p >= 0 && p < N_EDGES) {
            g_csr[p] = s;
            g_w[p] = g_dinv[s] * g_dinv[d];
        }
    }
}

// ---------------- SGEMM 64x64x8, double-buffered, f32x2 FMA -------------------
__global__ __launch_bounds__(256) void sgemm64(const float* __restrict__ A,
                                               const float* __restrict__ B,
                                               float* __restrict__ C, int M) {
    const int K = DIM, N = DIM, BM = 64, BN = 64, BK = 8;
    __shared__ __align__(16) float As[2][BK][BM];
    __shared__ __align__(16) float Bs[2][BK][BN];
    const int tid = threadIdx.x;
    const int rowBase = blockIdx.y * BM;
    const int colBase = blockIdx.x * BN;

    const bool loadA = tid < 128;
    const int aRow = tid >> 1;
    const int aCol = (tid & 1) * 4;
    const int bIdx = tid - 128;
    const int bRow = bIdx >> 4;
    const int bCol = (bIdx & 15) * 4;
    const int tRow = (tid >> 4) * 4;
    const int tCol = (tid & 15) * 4;

    u64 acc[4][2];
#pragma unroll
    for (int m = 0; m < 4; m++) { acc[m][0] = 0ull; acc[m][1] = 0ull; }

    float4 pa = make_float4(0.f, 0.f, 0.f, 0.f);
    float4 pb = pa;
    if (loadA) {
        int r = rowBase + aRow;
        if (r < M) pa = *reinterpret_cast<const float4*>(&A[r * K + aCol]);
    } else {
        pb = *reinterpret_cast<const float4*>(&B[bRow * N + colBase + bCol]);
    }
    if (loadA) {
        As[0][aCol + 0][aRow] = pa.x;
        As[0][aCol + 1][aRow] = pa.y;
        As[0][aCol + 2][aRow] = pa.z;
        As[0][aCol + 3][aRow] = pa.w;
    } else {
        *reinterpret_cast<float4*>(&Bs[0][bRow][bCol]) = pb;
    }
    __syncthreads();

    int cur = 0;
    for (int k0 = 0; k0 < K; k0 += BK) {
        const bool more = (k0 + BK) < K;
        if (more) {
            if (loadA) {
                int r = rowBase + aRow;
                pa = make_float4(0.f, 0.f, 0.f, 0.f);
                if (r < M)
                    pa = *reinterpret_cast<const float4*>(&A[r * K + k0 + BK + aCol]);
            } else {
                pb = *reinterpret_cast<const float4*>(
                    &B[(k0 + BK + bRow) * N + colBase + bCol]);
            }
        }
#pragma unroll
        for (int k = 0; k < BK; k++) {
            float4 a4 = *reinterpret_cast<float4*>(&As[cur][k][tRow]);
            u64 b0 = *reinterpret_cast<u64*>(&Bs[cur][k][tCol]);
            u64 b1 = *reinterpret_cast<u64*>(&Bs[cur][k][tCol + 2]);
            u64 m0 = pack2(a4.x, a4.x);
            u64 m1 = pack2(a4.y, a4.y);
            u64 m2 = pack2(a4.z, a4.z);
            u64 m3 = pack2(a4.w, a4.w);
            acc[0][0] = ffma2(m0, b0, acc[0][0]);
            acc[0][1] = ffma2(m0, b1, acc[0][1]);
            acc[1][0] = ffma2(m1, b0, acc[1][0]);
            acc[1][1] = ffma2(m1, b1, acc[1][1]);
            acc[2][0] = ffma2(m2, b0, acc[2][0]);
            acc[2][1] = ffma2(m2, b1, acc[2][1]);
            acc[3][0] = ffma2(m3, b0, acc[3][0]);
            acc[3][1] = ffma2(m3, b1, acc[3][1]);
        }
        if (more) {
            if (loadA) {
                As[cur ^ 1][aCol + 0][aRow] = pa.x;
                As[cur ^ 1][aCol + 1][aRow] = pa.y;
                As[cur ^ 1][aCol + 2][aRow] = pa.z;
                As[cur ^ 1][aCol + 3][aRow] = pa.w;
            } else {
                *reinterpret_cast<float4*>(&Bs[cur ^ 1][bRow][bCol]) = pb;
            }
        }
        __syncthreads();
        cur ^= 1;
    }

#pragma unroll
    for (int m = 0; m < 4; m++) {
        int r = rowBase + tRow + m;
        if (r < M) {
            float2 p0 = unpack2(acc[m][0]);
            float2 p1 = unpack2(acc[m][1]);
            float4 o = make_float4(p0.x, p0.y, p1.x, p1.y);
            *reinterpret_cast<float4*>(&C[r * N + colBase + tCol]) = o;
        }
    }
}

// ---------------- aggregation ------------------------------------------------
template <int MODE>
__global__ __launch_bounds__(256) void agg_kernel(
    const float4* __restrict__ T4, const float4* __restrict__ bias4,
    const float4* __restrict__ resid4, float4* __restrict__ out4) {
    const int i = blockIdx.x;
    const int tid = threadIdx.x;
    const int d4 = tid & 63;
    const int eg = tid >> 6;
    const int e0 = g_off[i], e1 = g_off[i + 1];

    float4 a0 = make_float4(0.f, 0.f, 0.f, 0.f);
    float4 a1 = a0;
    int e = e0 + eg;
    for (; e + 4 < e1; e += 8) {
        int s0 = g_csr[e];
        float w0 = g_w[e];
        int s1 = g_csr[e + 4];
        float w1 = g_w[e + 4];
        float4 v0 = T4[s0 * 64 + d4];
        float4 v1 = T4[s1 * 64 + d4];
        a0.x = fmaf(w0, v0.x, a0.x); a0.y = fmaf(w0, v0.y, a0.y);
        a0.z = fmaf(w0, v0.z, a0.z); a0.w = fmaf(w0, v0.w, a0.w);
        a1.x = fmaf(w1, v1.x, a1.x); a1.y = fmaf(w1, v1.y, a1.y);
        a1.z = fmaf(w1, v1.z, a1.z); a1.w = fmaf(w1, v1.w, a1.w);
    }
    if (e < e1) {
        int s = g_csr[e];
        float w = g_w[e];
        float4 v = T4[s * 64 + d4];
        a0.x = fmaf(w, v.x, a0.x); a0.y = fmaf(w, v.y, a0.y);
        a0.z = fmaf(w, v.z, a0.z); a0.w = fmaf(w, v.w, a0.w);
    }
    a0.x += a1.x; a0.y += a1.y; a0.z += a1.z; a0.w += a1.w;

    __shared__ float4 part[3][64];
    if (eg > 0) part[eg - 1][d4] = a0;
    __syncthreads();
    if (eg == 0) {
        const float di = g_dinv[i];
        float4 self = T4[i * 64 + d4];
        float dii = di * di;
        float4 b = bias4[d4];
        float4 acc;
        acc.x = a0.x + part[0][d4].x + part[1][d4].x + part[2][d4].x + self.x * dii + b.x;
        acc.y = a0.y + part[0][d4].y + part[1][d4].y + part[2][d4].y + self.y * dii + b.y;
        acc.z = a0.z + part[0][d4].z + part[1][d4].z + part[2][d4].z + self.z * dii + b.z;
        acc.w = a0.w + part[0][d4].w + part[1][d4].w + part[2][d4].w + self.w * dii + b.w;
        if (MODE == 1) {
            float4 r = resid4[i * 64 + d4];
            acc.x += r.x; acc.y += r.y; acc.z += r.z; acc.w += r.w;
        }
        if (MODE <= 1) {
            acc.x = fmaxf(acc.x, 0.f); acc.y = fmaxf(acc.y, 0.f);
            acc.z = fmaxf(acc.z, 0.f); acc.w = fmaxf(acc.w, 0.f);
        }
        out4[i * 64 + d4] = acc;
    }
}

// ---------------- pooling: one block per graph, writes the MEAN --------------
__global__ __launch_bounds__(256) void pool_kernel(const float4* __restrict__ h4) {
    const int g = blockIdx.x;
    const int tid = threadIdx.x;
    const int d4 = tid & 63;
    const int rg = tid >> 6;
    const int r0 = g_gstart[g], r1 = g_gstart[g + 1];
    float4 acc = make_float4(0.f, 0.f, 0.f, 0.f);
    for (int i = r0 + rg; i < r1; i += 4) {
        float4 v = h4[i * 64 + d4];
        acc.x += v.x; acc.y += v.y; acc.z += v.z; acc.w += v.w;
    }
    __shared__ float4 part[4][64];
    part[rg][d4] = acc;
    __syncthreads();
    if (rg == 0) {
        float inv = 1.0f / fmaxf((float)(r1 - r0), 1.0f);
        float4 s;
        s.x = (part[0][d4].x + part[1][d4].x + part[2][d4].x + part[3][d4].x) * inv;
        s.y = (part[0][d4].y + part[1][d4].y + part[2][d4].y + part[3][d4].y) * inv;
        s.z = (part[0][d4].z + part[1][d4].z + part[2][d4].z + part[3][d4].z) * inv;
        s.w = (part[0][d4].w + part[1][d4].w + part[2][d4].w + part[3][d4].w) * inv;
        reinterpret_cast<float4*>(g_pool)[g * 64 + d4] = s;
    }
}

// ---------------- classifier + log_softmax ------------------------------------
__global__ __launch_bounds__(256) void cls_kernel(const float* __restrict__ Wc,
                                                  const float* __restrict__ bc,
                                                  float* __restrict__ out,
                                                  int out_size) {
    const int g = blockIdx.x;
    const int t = threadIdx.x;
    __shared__ float p[DIM];
    __shared__ float logits[N_CLASSES];
    p[t] = g_pool[g * DIM + t];
    __syncthreads();
    const int w = t >> 5, lane = t & 31;
    for (int cls = w; cls < N_CLASSES; cls += 8) {
        float s = 0.0f;
        for (int k = lane; k < DIM; k += 32) s += p[k] * Wc[k * N_CLASSES + cls];
#pragma unroll
        for (int o = 16; o; o >>= 1) s += __shfl_xor_sync(0xffffffffu, s, o);
        if (lane == 0) logits[cls] = s + bc[cls];
    }
    __syncthreads();
    if (t < N_CLASSES) {
        float mx = -1e30f;
#pragma unroll
        for (int k = 0; k < N_CLASSES; k++) mx = fmaxf(mx, logits[k]);
        float sum = 0.0f;
#pragma unroll
        for (int k = 0; k < N_CLASSES; k++) sum += expf(logits[k] - mx);
        float lse = mx + logf(sum);
        out[g * N_CLASSES + t] = logits[t];
        if (out_size >= 2 * N_GRAPHS * N_CLASSES)
            out[N_GRAPHS * N_CLASSES + g * N_CLASSES + t] = logits[t] - lse;
    }
}

// ---------------- launch -------------------------------------------------------
extern "C" void kernel_launch(void* const* d_in, const int* in_sizes, int n_in,
                              void* d_out, int out_size) {
    const float* x = (const float*)d_in[0];
    const void*  ei = d_in[1];
    const void*  batch = d_in[2];
    const float* W1 = (const float*)d_in[3];
    const float* b1 = (const float*)d_in[4];
    const float* W2 = (const float*)d_in[5];
    const float* b2 = (const float*)d_in[6];
    const float* W3 = (const float*)d_in[7];
    const float* b3 = (const float*)d_in[8];
    const float* Wc = (const float*)d_in[9];
    const float* bc = (const float*)d_in[10];
    float* out = (float*)d_out;

    float* T; float* A; float* B;
    cudaGetSymbolAddress((void**)&T, g_T);
    cudaGetSymbolAddress((void**)&A, g_A);
    cudaGetSymbolAddress((void**)&B, g_B);

    detect_kernel<<<1, 1024>>>(ei, batch);
    convert_batch_kernel<<<(N_NODES + 255) / 256, 256>>>(batch);
    convert_edges_kernel<<<(N_EDGES + 255) / 256, 256>>>(ei);
    scan_pre<<<N_SCANB, SCAN_BLK>>>();
    scan_mid<<<1, 128>>>();
    scan_post<<<N_SCANB, SCAN_BLK>>>();
    fill_kernel<<<(N_EDGES + 255) / 256, 256>>>();

    dim3 ggrid(DIM / 64, (N_NODES + 63) / 64);

    sgemm64<<<ggrid, 256>>>(x, W1, T, N_NODES);
    agg_kernel<0><<<N_NODES, 256>>>((const float4*)T, (const float4*)b1, nullptr,
                                    (float4*)A);
    sgemm64<<<ggrid, 256>>>(A, W2, T, N_NODES);
    agg_kernel<1><<<N_NODES, 256>>>((const float4*)T, (const float4*)b2,
                                    (const float4*)A, (float4*)B);
    sgemm64<<<ggrid, 256>>>(B, W3, T, N_NODES);
    agg_kernel<2><<<N_NODES, 256>>>((const float4*)T, (const float4*)b3, nullptr,
                                    (float4*)A);

    pool_kernel<<<N_GRAPHS, 256>>>((const float4*)A);
    cls_kernel<<<N_GRAPHS, 256>>>(Wc, bc, out, out_size);
}

// round 7
// speedup vs baseline: 1.3824x; 1.0354x over previous
#include <cuda_runtime.h>
#include <cuda_bf16.h>
#include <mma.h>
#include <math.h>
#include <stdint.h>

using namespace nvcuda;

// ---------------------------------------------------------------------------
// GCN_9062380994846: 3-layer GCN + mean pool + classifier + log_softmax
// GEMMs on tensor cores via WMMA bf16 (hi/lo split, K'=768, fp32 accum)
// ---------------------------------------------------------------------------

#define N_NODES   20000
#define N_EDGES   320000
#define DIM       256
#define N_GRAPHS  64
#define N_CLASSES 10
#define SCAN_BLK  256
#define N_SCANB   ((N_NODES + SCAN_BLK - 1) / SCAN_BLK)   // 79
#define PAD_M     20096                                    // 157 * 128
#define KP        768                                      // 3 * 256

// ---------------- scratch ----------------------------------------------------
__device__ float g_T[PAD_M * DIM];
__device__ float g_A[PAD_M * DIM];
__device__ float g_B[PAD_M * DIM];
__device__ __nv_bfloat16 g_Ahi[PAD_M * DIM];
__device__ __nv_bfloat16 g_Alo[PAD_M * DIM];
__device__ __nv_bfloat16 g_Bext[3 * KP * DIM];   // [layer][768][256]: hi;lo;hi
__device__ int   g_src32[N_EDGES];
__device__ int   g_dst32[N_EDGES];
__device__ int   g_cnt[N_NODES];
__device__ int   g_off[N_NODES + 1];
__device__ int   g_cur[N_NODES];
__device__ int   g_csr[N_EDGES];
__device__ float g_w[N_EDGES];
__device__ float g_dinv[N_NODES];
__device__ int   g_bsum[N_SCANB];
__device__ int   g_bbase[N_SCANB];
__device__ int   g_gstart[N_GRAPHS + 1];
__device__ float g_pool[N_GRAPHS * DIM];
__device__ int   g_ei_is64;
__device__ int   g_b_is64;

// ---------------- dtype detection (sampling only) -----------------------------
__global__ void detect_kernel(const void* ei, const void* batch) {
    int t = threadIdx.x;  // 1024 threads
    if (t == 0) { g_ei_is64 = 1; g_b_is64 = 1; }
    __syncthreads();
    long long v = ((const long long*)ei)[(long long)t * 312];
    if (v < 0 || v >= N_NODES) atomicExch(&g_ei_is64, 0);
    long long b = ((const long long*)batch)[t * 9];
    if (b < 0 || b >= N_GRAPHS) atomicExch(&g_b_is64, 0);
}

// ---------------- fp32 -> bf16 hi/lo conversion --------------------------------
__global__ __launch_bounds__(256) void convert_in(const float4* __restrict__ src) {
    int i = blockIdx.x * 256 + threadIdx.x;  // group of 4 floats
    if (i >= PAD_M * 64) return;
    int row = i >> 6;
    float4 v = make_float4(0.f, 0.f, 0.f, 0.f);
    if (row < N_NODES) v = src[i];
    __nv_bfloat162 h0 = __floats2bfloat162_rn(v.x, v.y);
    __nv_bfloat162 h1 = __floats2bfloat162_rn(v.z, v.w);
    float l0 = v.x - __low2float(h0);
    float l1 = v.y - __high2float(h0);
    float l2 = v.z - __low2float(h1);
    float l3 = v.w - __high2float(h1);
    ((__nv_bfloat162*)g_Ahi)[2 * i]     = h0;
    ((__nv_bfloat162*)g_Ahi)[2 * i + 1] = h1;
    ((__nv_bfloat162*)g_Alo)[2 * i]     = __floats2bfloat162_rn(l0, l1);
    ((__nv_bfloat162*)g_Alo)[2 * i + 1] = __floats2bfloat162_rn(l2, l3);
}

// Bext[layer] = [hi(W); lo(W); hi(W)]  (768 x 256 bf16, row-major, NOT transposed)
__global__ __launch_bounds__(256) void convert_w(const float* __restrict__ W1,
                                                 const float* __restrict__ W2,
                                                 const float* __restrict__ W3) {
    int i = blockIdx.x * 256 + threadIdx.x;
    if (i >= 3 * DIM * DIM) return;
    int w = i >> 16, r = i & 0xFFFF;
    int k = r >> 8, n = r & 255;
    const float* W = (w == 0) ? W1 : (w == 1) ? W2 : W3;
    float v = W[k * DIM + n];
    __nv_bfloat16 h = __float2bfloat16(v);
    __nv_bfloat16 l = __float2bfloat16(v - __bfloat162float(h));
    __nv_bfloat16* Be = g_Bext + w * KP * DIM;
    Be[k * DIM + n] = h;
    Be[(256 + k) * DIM + n] = l;
    Be[(512 + k) * DIM + n] = h;
}

// ---------------- WMMA GEMM: C[PAD_M,256] = [Ahi|Ahi|Alo] @ Bext ----------------
// BM=128, BN=128, BK=32, K'=768 (24 chunks). 8 warps: 4 in M x 2 in N,
// warp tile 32x64 (acc 2x4 of 16x16). Double-buffered smem, 1 sync/chunk.
#define GBM 128
#define GBN 128
#define GBK 32
#define NCHUNK (KP / GBK)   // 24

__global__ __launch_bounds__(256, 2) void gemm_wmma(int layer, float* __restrict__ C) {
    __shared__ __align__(16) __nv_bfloat16 As[2][GBM][GBK + 8];
    __shared__ __align__(16) __nv_bfloat16 Bs[2][GBK][GBN + 8];
    const int tid = threadIdx.x;
    const int wid = tid >> 5;
    const int wm = wid & 3;          // 0..3 -> rows wm*32
    const int wn = wid >> 2;         // 0..1 -> cols wn*64
    const int rowBase = blockIdx.y * GBM;
    const int colBase = blockIdx.x * GBN;
    const __nv_bfloat16* Bext = g_Bext + layer * KP * DIM;

    // A: 128 rows x 32 cols -> 512 uint4, 2 per thread
    const int ar0 = tid >> 2, as0 = (tid & 3) * 8;            // q = tid
    const int ar1 = (tid + 256) >> 2, as1 = as0;              // q = tid+256
    // B: 32 rows x 128 cols -> 512 uint4, 2 per thread
    const int br0 = tid >> 4, bs0 = (tid & 15) * 8;
    const int br1 = (tid + 256) >> 4, bs1 = bs0;

    wmma::fragment<wmma::accumulator, 16, 16, 16, float> acc[2][4];
#pragma unroll
    for (int i = 0; i < 2; i++)
#pragma unroll
        for (int j = 0; j < 4; j++) wmma::fill_fragment(acc[i][j], 0.0f);

    auto a_src = [&](int c) -> const __nv_bfloat16* {
        int kc = c * GBK;
        return (kc < 512) ? (g_Ahi + (kc & 255)) : (g_Alo + (kc - 512));
    };

    // preload chunk 0
    {
        const __nv_bfloat16* Ap = a_src(0);
        *(uint4*)&As[0][ar0][as0] = *(const uint4*)&Ap[(rowBase + ar0) * DIM + as0];
        *(uint4*)&As[0][ar1][as1] = *(const uint4*)&Ap[(rowBase + ar1) * DIM + as1];
        *(uint4*)&Bs[0][br0][bs0] = *(const uint4*)&Bext[br0 * DIM + colBase + bs0];
        *(uint4*)&Bs[0][br1][bs1] = *(const uint4*)&Bext[br1 * DIM + colBase + bs1];
    }
    __syncthreads();

    for (int c = 0; c < NCHUNK; c++) {
        const int s = c & 1;
        // prefetch chunk c+1 into the other buffer (no conflict with compute on s)
        if (c + 1 < NCHUNK) {
            const __nv_bfloat16* Ap = a_src(c + 1);
            int kc = (c + 1) * GBK;
            uint4 a0 = *(const uint4*)&Ap[(rowBase + ar0) * DIM + as0];
            uint4 a1 = *(const uint4*)&Ap[(rowBase + ar1) * DIM + as1];
            uint4 b0 = *(const uint4*)&Bext[(kc + br0) * DIM + colBase + bs0];
            uint4 b1 = *(const uint4*)&Bext[(kc + br1) * DIM + colBase + bs1];
            *(uint4*)&As[s ^ 1][ar0][as0] = a0;
            *(uint4*)&As[s ^ 1][ar1][as1] = a1;
            *(uint4*)&Bs[s ^ 1][br0][bs0] = b0;
            *(uint4*)&Bs[s ^ 1][br1][bs1] = b1;
        }
#pragma unroll
        for (int ks = 0; ks < GBK; ks += 16) {
            wmma::fragment<wmma::matrix_a, 16, 16, 16, __nv_bfloat16, wmma::row_major> af[2];
            wmma::fragment<wmma::matrix_b, 16, 16, 16, __nv_bfloat16, wmma::row_major> bf[4];
#pragma unroll
            for (int i = 0; i < 2; i++)
                wmma::load_matrix_sync(af[i], &As[s][wm * 32 + i * 16][ks], GBK + 8);
#pragma unroll
            for (int j = 0; j < 4; j++)
                wmma::load_matrix_sync(bf[j], &Bs[s][ks][wn * 64 + j * 16], GBN + 8);
#pragma unroll
            for (int i = 0; i < 2; i++)
#pragma unroll
                for (int j = 0; j < 4; j++)
                    wmma::mma_sync(acc[i][j], af[i], bf[j], acc[i][j]);
        }
        __syncthreads();
    }

#pragma unroll
    for (int i = 0; i < 2; i++)
#pragma unroll
        for (int j = 0; j < 4; j++)
            wmma::store_matrix_sync(
                &C[(rowBase + wm * 32 + i * 16) * DIM + colBase + wn * 64 + j * 16],
                acc[i][j], DIM, wmma::mem_row_major);
}

// ---------------- graph preprocessing ------------------------------------------
__global__ void convert_batch_kernel(const void* batch) {
    int i = blockIdx.x * blockDim.x + threadIdx.x;
    if (i >= N_NODES) return;
    g_cnt[i] = 0;
    if (i <= N_GRAPHS) g_gstart[i] = N_NODES;
    int b = g_b_is64 ? (int)((const long long*)batch)[i] : ((const int*)batch)[i];
    b = min(max(b, 0), N_GRAPHS - 1);
    atomicMin(&g_gstart[b], i);
}

__global__ void convert_edges_kernel(const void* ei) {
    int e = blockIdx.x * blockDim.x + threadIdx.x;
    if (e >= N_EDGES) return;
    int s, d;
    if (g_ei_is64) {
        s = (int)((const long long*)ei)[e];
        d = (int)((const long long*)ei)[N_EDGES + e];
    } else {
        s = ((const int*)ei)[e];
        d = ((const int*)ei)[N_EDGES + e];
    }
    s = min(max(s, 0), N_NODES - 1);
    d = min(max(d, 0), N_NODES - 1);
    g_src32[e] = s;
    g_dst32[e] = d;
    atomicAdd(&g_cnt[d], 1);
}

__global__ __launch_bounds__(SCAN_BLK) void scan_pre() {
    const int t = threadIdx.x;
    int i = blockIdx.x * SCAN_BLK + t;
    int v = (i < N_NODES) ? g_cnt[i] : 0;
#pragma unroll
    for (int o = 16; o; o >>= 1) v += __shfl_xor_sync(0xffffffffu, v, o);
    __shared__ int ws[8];
    if ((t & 31) == 0) ws[t >> 5] = v;
    __syncthreads();
    if (t < 8) {
        int s = ws[t];
#pragma unroll
        for (int o = 4; o; o >>= 1) s += __shfl_xor_sync(0xffu, s, o);
        if (t == 0) g_bsum[blockIdx.x] = s;
    }
}

__global__ void scan_mid() {
    const int t = threadIdx.x;  // 128
    __shared__ int s[128];
    int v = (t < N_SCANB) ? g_bsum[t] : 0;
    s[t] = v;
    __syncthreads();
    for (int o = 1; o < 128; o <<= 1) {
        int u = (t >= o) ? s[t - o] : 0;
        __syncthreads();
        s[t] += u;
        __syncthreads();
    }
    if (t < N_SCANB) g_bbase[t] = s[t] - v;
    if (t == 0) g_off[N_NODES] = s[N_SCANB - 1];
    if (t == 64) {
        g_gstart[N_GRAPHS] = N_NODES;
        for (int g = N_GRAPHS - 1; g >= 0; g--)
            g_gstart[g] = min(g_gstart[g], g_gstart[g + 1]);
    }
}

__global__ __launch_bounds__(SCAN_BLK) void scan_post() {
    const int t = threadIdx.x;
    int i = blockIdx.x * SCAN_BLK + t;
    int c = (i < N_NODES) ? g_cnt[i] : 0;
    int v = c;
#pragma unroll
    for (int o = 1; o < 32; o <<= 1) {
        int u = __shfl_up_sync(0xffffffffu, v, o);
        if ((t & 31) >= o) v += u;
    }
    __shared__ int ws[8];
    if ((t & 31) == 31) ws[t >> 5] = v;
    __syncthreads();
    if (t < 8) {
        int s = ws[t];
#pragma unroll
        for (int o = 1; o < 8; o <<= 1) {
            int u = __shfl_up_sync(0xffu, s, o);
            if (t >= o) s += u;
        }
        ws[t] = s;
    }
    __syncthreads();
    int warpBase = (t >= 32) ? ws[(t >> 5) - 1] : 0;
    int excl = g_bbase[blockIdx.x] + warpBase + v - c;
    if (i < N_NODES) {
        g_off[i] = excl;
        g_cur[i] = excl;
        g_dinv[i] = rsqrtf((float)c + 1.0f);
    }
}

__global__ void fill_kernel() {
    int e = blockIdx.x * blockDim.x + threadIdx.x;
    if (e < N_EDGES) {
        int s = g_src32[e];
        int d = g_dst32[e];
        int p = atomicAdd(&g_cur[d], 1);
        if (p >= 0 && p < N_EDGES) {
            g_csr[p] = s;
            g_w[p] = g_dinv[s] * g_dinv[d];
        }
    }
}

// ---------------- aggregation ------------------------------------------------
template <int MODE>
__global__ __launch_bounds__(256) void agg_kernel(
    const float4* __restrict__ T4, const float4* __restrict__ bias4,
    const float4* __restrict__ resid4, float4* __restrict__ out4) {
    const int i = blockIdx.x;
    const int tid = threadIdx.x;
    const int d4 = tid & 63;
    const int eg = tid >> 6;
    const int e0 = g_off[i], e1 = g_off[i + 1];

    float4 a0 = make_float4(0.f, 0.f, 0.f, 0.f);
    float4 a1 = a0;
    int e = e0 + eg;
    for (; e + 4 < e1; e += 8) {
        int s0 = g_csr[e];
        float w0 = g_w[e];
        int s1 = g_csr[e + 4];
        float w1 = g_w[e + 4];
        float4 v0 = T4[s0 * 64 + d4];
        float4 v1 = T4[s1 * 64 + d4];
        a0.x = fmaf(w0, v0.x, a0.x); a0.y = fmaf(w0, v0.y, a0.y);
        a0.z = fmaf(w0, v0.z, a0.z); a0.w = fmaf(w0, v0.w, a0.w);
        a1.x = fmaf(w1, v1.x, a1.x); a1.y = fmaf(w1, v1.y, a1.y);
        a1.z = fmaf(w1, v1.z, a1.z); a1.w = fmaf(w1, v1.w, a1.w);
    }
    if (e < e1) {
        int s = g_csr[e];
        float w = g_w[e];
        float4 v = T4[s * 64 + d4];
        a0.x = fmaf(w, v.x, a0.x); a0.y = fmaf(w, v.y, a0.y);
        a0.z = fmaf(w, v.z, a0.z); a0.w = fmaf(w, v.w, a0.w);
    }
    a0.x += a1.x; a0.y += a1.y; a0.z += a1.z; a0.w += a1.w;

    __shared__ float4 part[3][64];
    if (eg > 0) part[eg - 1][d4] = a0;
    __syncthreads();
    if (eg == 0) {
        const float di = g_dinv[i];
        float4 self = T4[i * 64 + d4];
        float dii = di * di;
        float4 b = bias4[d4];
        float4 acc;
        acc.x = a0.x + part[0][d4].x + part[1][d4].x + part[2][d4].x + self.x * dii + b.x;
        acc.y = a0.y + part[0][d4].y + part[1][d4].y + part[2][d4].y + self.y * dii + b.y;
        acc.z = a0.z + part[0][d4].z + part[1][d4].z + part[2][d4].z + self.z * dii + b.z;
        acc.w = a0.w + part[0][d4].w + part[1][d4].w + part[2][d4].w + self.w * dii + b.w;
        if (MODE == 1) {
            float4 r = resid4[i * 64 + d4];
            acc.x += r.x; acc.y += r.y; acc.z += r.z; acc.w += r.w;
        }
        if (MODE <= 1) {
            acc.x = fmaxf(acc.x, 0.f); acc.y = fmaxf(acc.y, 0.f);
            acc.z = fmaxf(acc.z, 0.f); acc.w = fmaxf(acc.w, 0.f);
        }
        out4[i * 64 + d4] = acc;
    }
}

// ---------------- pooling ------------------------------------------------------
__global__ __launch_bounds__(256) void pool_kernel(const float4* __restrict__ h4) {
    const int g = blockIdx.x;
    const int tid = threadIdx.x;
    const int d4 = tid & 63;
    const int rg = tid >> 6;
    const int r0 = g_gstart[g], r1 = g_gstart[g + 1];
    float4 acc = make_float4(0.f, 0.f, 0.f, 0.f);
    for (int i = r0 + rg; i < r1; i += 4) {
        float4 v = h4[i * 64 + d4];
        acc.x += v.x; acc.y += v.y; acc.z += v.z; acc.w += v.w;
    }
    __shared__ float4 part[4][64];
    part[rg][d4] = acc;
    __syncthreads();
    if (rg == 0) {
        float inv = 1.0f / fmaxf((float)(r1 - r0), 1.0f);
        float4 s;
        s.x = (part[0][d4].x + part[1][d4].x + part[2][d4].x + part[3][d4].x) * inv;
        s.y = (part[0][d4].y + part[1][d4].y + part[2][d4].y + part[3][d4].y) * inv;
        s.z = (part[0][d4].z + part[1][d4].z + part[2][d4].z + part[3][d4].z) * inv;
        s.w = (part[0][d4].w + part[1][d4].w + part[2][d4].w + part[3][d4].w) * inv;
        reinterpret_cast<float4*>(g_pool)[g * 64 + d4] = s;
    }
}

// ---------------- classifier + log_softmax -------------------------------------
__global__ __launch_bounds__(256) void cls_kernel(const float* __restrict__ Wc,
                                                  const float* __restrict__ bc,
                                                  float* __restrict__ out,
                                                  int out_size) {
    const int g = blockIdx.x;
    const int t = threadIdx.x;
    __shared__ float p[DIM];
    __shared__ float logits[N_CLASSES];
    p[t] = g_pool[g * DIM + t];
    __syncthreads();
    const int w = t >> 5, lane = t & 31;
    for (int cls = w; cls < N_CLASSES; cls += 8) {
        float s = 0.0f;
        for (int k = lane; k < DIM; k += 32) s += p[k] * Wc[k * N_CLASSES + cls];
#pragma unroll
        for (int o = 16; o; o >>= 1) s += __shfl_xor_sync(0xffffffffu, s, o);
        if (lane == 0) logits[cls] = s + bc[cls];
    }
    __syncthreads();
    if (t < N_CLASSES) {
        float mx = -1e30f;
#pragma unroll
        for (int k = 0; k < N_CLASSES; k++) mx = fmaxf(mx, logits[k]);
        float sum = 0.0f;
#pragma unroll
        for (int k = 0; k < N_CLASSES; k++) sum += expf(logits[k] - mx);
        float lse = mx + logf(sum);
        out[g * N_CLASSES + t] = logits[t];
        if (out_size >= 2 * N_GRAPHS * N_CLASSES)
            out[N_GRAPHS * N_CLASSES + g * N_CLASSES + t] = logits[t] - lse;
    }
}

// ---------------- launch ---------------------------------------------------------
extern "C" void kernel_launch(void* const* d_in, const int* in_sizes, int n_in,
                              void* d_out, int out_size) {
    const float* x = (const float*)d_in[0];
    const void*  ei = d_in[1];
    const void*  batch = d_in[2];
    const float* W1 = (const float*)d_in[3];
    const float* b1 = (const float*)d_in[4];
    const float* W2 = (const float*)d_in[5];
    const float* b2 = (const float*)d_in[6];
    const float* W3 = (const float*)d_in[7];
    const float* b3 = (const float*)d_in[8];
    const float* Wc = (const float*)d_in[9];
    const float* bc = (const float*)d_in[10];
    float* out = (float*)d_out;

    float* T; float* A; float* B;
    cudaGetSymbolAddress((void**)&T, g_T);
    cudaGetSymbolAddress((void**)&A, g_A);
    cudaGetSymbolAddress((void**)&B, g_B);

    const int CONV_GRID = (PAD_M * 64 + 255) / 256;
    const dim3 ggrid(DIM / GBN, PAD_M / GBM);  // (2, 157)

    // idx 0-2
    detect_kernel<<<1, 1024>>>(ei, batch);
    convert_in<<<CONV_GRID, 256>>>((const float4*)x);
    convert_w<<<(3 * DIM * DIM + 255) / 256, 256>>>(W1, W2, W3);
    // idx 3: layer-1 GEMM — profiled slot
    gemm_wmma<<<ggrid, 256>>>(0, T);
    // graph preprocessing
    convert_batch_kernel<<<(N_NODES + 255) / 256, 256>>>(batch);
    convert_edges_kernel<<<(N_EDGES + 255) / 256, 256>>>(ei);
    scan_pre<<<N_SCANB, SCAN_BLK>>>();
    scan_mid<<<1, 128>>>();
    scan_post<<<N_SCANB, SCAN_BLK>>>();
    fill_kernel<<<(N_EDGES + 255) / 256, 256>>>();
    // layer 1 aggregate
    agg_kernel<0><<<N_NODES, 256>>>((const float4*)T, (const float4*)b1, nullptr,
                                    (float4*)A);
    // layer 2
    convert_in<<<CONV_GRID, 256>>>((const float4*)A);
    gemm_wmma<<<ggrid, 256>>>(1, T);
    agg_kernel<1><<<N_NODES, 256>>>((const float4*)T, (const float4*)b2,
                                    (const float4*)A, (float4*)B);
    // layer 3
    convert_in<<<CONV_GRID, 256>>>((const float4*)B);
    gemm_wmma<<<ggrid, 256>>>(2, T);
    agg_kernel<2><<<N_NODES, 256>>>((const float4*)T, (const float4*)b3, nullptr,
                                    (float4*)A);

    pool_kernel<<<N_GRAPHS, 256>>>((const float4*)A);
    cls_kernel<<<N_GRAPHS, 256>>>(Wc, bc, out, out_size);
}

// round 8
// speedup vs baseline: 1.4466x; 1.0464x over previous
#include <cuda_runtime.h>
#include <cuda_bf16.h>
#include <mma.h>
#include <math.h>
#include <stdint.h>

using namespace nvcuda;

// ---------------------------------------------------------------------------
// GCN_9062380994846: 3-layer GCN + mean pool + classifier + log_softmax
// GEMMs: WMMA bf16 hi/lo split (K'=768), cp.async double-buffered, BN=256
// ---------------------------------------------------------------------------

#define N_NODES   20000
#define N_EDGES   320000
#define DIM       256
#define N_GRAPHS  64
#define N_CLASSES 10
#define SCAN_BLK  256
#define N_SCANB   ((N_NODES + SCAN_BLK - 1) / SCAN_BLK)   // 79
#define PAD_M     20096                                    // 157 * 128
#define KP        768

// ---------------- scratch ----------------------------------------------------
__device__ float g_T[PAD_M * DIM];
__device__ float g_A[PAD_M * DIM];
__device__ float g_B[PAD_M * DIM];
__device__ __nv_bfloat16 g_Ahi[PAD_M * DIM];
__device__ __nv_bfloat16 g_Alo[PAD_M * DIM];
__device__ __nv_bfloat16 g_Bext[3 * KP * DIM];   // [layer][768][256]: hi;lo;hi
__device__ int   g_src32[N_EDGES];
__device__ int   g_dst32[N_EDGES];
__device__ int   g_cnt[N_NODES];
__device__ int   g_off[N_NODES + 1];
__device__ int   g_cur[N_NODES];
__device__ int   g_csr[N_EDGES];
__device__ float g_w[N_EDGES];
__device__ float g_dinv[N_NODES];
__device__ int   g_bsum[N_SCANB];
__device__ int   g_bbase[N_SCANB];
__device__ int   g_gstart[N_GRAPHS + 1];
__device__ float g_pool[N_GRAPHS * DIM];
__device__ int   g_ei_is64;
__device__ int   g_b_is64;

// ---------------- cp.async helpers ---------------------------------------------
__device__ __forceinline__ void cpa16(uint32_t dst, const void* src) {
    asm volatile("cp.async.cg.shared.global [%0], [%1], 16;" :: "r"(dst), "l"(src));
}
#define CP_COMMIT() asm volatile("cp.async.commit_group;" ::: "memory")
#define CP_WAIT(N)  asm volatile("cp.async.wait_group %0;" :: "n"(N) : "memory")

// ---------------- dtype detection ----------------------------------------------
__global__ void detect_kernel(const void* ei, const void* batch) {
    int t = threadIdx.x;
    if (t == 0) { g_ei_is64 = 1; g_b_is64 = 1; }
    __syncthreads();
    long long v = ((const long long*)ei)[(long long)t * 312];
    if (v < 0 || v >= N_NODES) atomicExch(&g_ei_is64, 0);
    long long b = ((const long long*)batch)[t * 9];
    if (b < 0 || b >= N_GRAPHS) atomicExch(&g_b_is64, 0);
}

// ---------------- fp32 -> bf16 hi/lo (x only; layers 2-3 fused into agg) -------
__global__ __launch_bounds__(256) void convert_in(const float4* __restrict__ src) {
    int i = blockIdx.x * 256 + threadIdx.x;
    if (i >= PAD_M * 64) return;
    int row = i >> 6;
    float4 v = make_float4(0.f, 0.f, 0.f, 0.f);
    if (row < N_NODES) v = src[i];
    __nv_bfloat162 h0 = __floats2bfloat162_rn(v.x, v.y);
    __nv_bfloat162 h1 = __floats2bfloat162_rn(v.z, v.w);
    float l0 = v.x - __low2float(h0);
    float l1 = v.y - __high2float(h0);
    float l2 = v.z - __low2float(h1);
    float l3 = v.w - __high2float(h1);
    ((__nv_bfloat162*)g_Ahi)[2 * i]     = h0;
    ((__nv_bfloat162*)g_Ahi)[2 * i + 1] = h1;
    ((__nv_bfloat162*)g_Alo)[2 * i]     = __floats2bfloat162_rn(l0, l1);
    ((__nv_bfloat162*)g_Alo)[2 * i + 1] = __floats2bfloat162_rn(l2, l3);
}

__global__ __launch_bounds__(256) void convert_w(const float* __restrict__ W1,
                                                 const float* __restrict__ W2,
                                                 const float* __restrict__ W3) {
    int i = blockIdx.x * 256 + threadIdx.x;
    if (i >= 3 * DIM * DIM) return;
    int w = i >> 16, r = i & 0xFFFF;
    int k = r >> 8, n = r & 255;
    const float* W = (w == 0) ? W1 : (w == 1) ? W2 : W3;
    float v = W[k * DIM + n];
    __nv_bfloat16 h = __float2bfloat16(v);
    __nv_bfloat16 l = __float2bfloat16(v - __bfloat162float(h));
    __nv_bfloat16* Be = g_Bext + w * KP * DIM;
    Be[k * DIM + n] = h;
    Be[(256 + k) * DIM + n] = l;
    Be[(512 + k) * DIM + n] = h;
}

// ---------------- WMMA GEMM: C[PAD_M,256] = [Ahi|Ahi|Alo] @ Bext ----------------
// BM=128, BN=256 (full N), BK=64, 12 chunks double-buffered via cp.async.
// 8 warps: 2(M) x 4(N), warp tile 64x64, acc 4x4.
#define GBM 128
#define GBN 256
#define GBK 64
#define NCHUNK (KP / GBK)         // 12
#define A_LD  (GBK + 8)           // 72
#define B_LD  (GBN + 8)           // 264
#define A_SZ  (GBM * A_LD * 2)    // 18432 B
#define B_SZ  (GBK * B_LD * 2)    // 33792 B
#define GEMM_SMEM (2 * (A_SZ + B_SZ))  // 104448 B

__global__ __launch_bounds__(256, 1) void gemm_wmma(int layer, float* __restrict__ C) {
    extern __shared__ __align__(16) char smem[];
    const int tid = threadIdx.x;
    const int wid = tid >> 5;
    const int wm = wid & 1;          // 0..1 -> 64-row stripe
    const int wn = wid >> 1;         // 0..3 -> 64-col stripe
    const int rowBase = blockIdx.x * GBM;
    const __nv_bfloat16* Bext = g_Bext + layer * KP * DIM;

    __nv_bfloat16* As[2] = {(__nv_bfloat16*)smem, (__nv_bfloat16*)(smem + A_SZ)};
    __nv_bfloat16* Bs[2] = {(__nv_bfloat16*)(smem + 2 * A_SZ),
                            (__nv_bfloat16*)(smem + 2 * A_SZ + B_SZ)};

    auto prefetch = [&](int c) {
        const int s = c & 1;
        const __nv_bfloat16* Ap = (c < 8) ? g_Ahi : g_Alo;
        const int ko = (c & 3) * GBK;
        // A: 128 rows x 64 cols = 1024 x 16B, 4 per thread
        uint32_t abase = (uint32_t)__cvta_generic_to_shared(As[s]);
#pragma unroll
        for (int t = 0; t < 4; t++) {
            int q = tid + t * 256;
            int row = q >> 3, seg = q & 7;
            cpa16(abase + (row * A_LD + seg * 8) * 2,
                  Ap + (rowBase + row) * DIM + ko + seg * 8);
        }
        // B: 64 rows x 256 cols = 2048 x 16B, 8 per thread
        uint32_t bbase = (uint32_t)__cvta_generic_to_shared(Bs[s]);
#pragma unroll
        for (int t = 0; t < 8; t++) {
            int q = tid + t * 256;
            int row = q >> 5, seg = q & 31;
            cpa16(bbase + (row * B_LD + seg * 8) * 2,
                  Bext + (c * GBK + row) * DIM + seg * 8);
        }
        CP_COMMIT();
    };

    wmma::fragment<wmma::accumulator, 16, 16, 16, float> acc[4][4];
#pragma unroll
    for (int i = 0; i < 4; i++)
#pragma unroll
        for (int j = 0; j < 4; j++) wmma::fill_fragment(acc[i][j], 0.0f);

    prefetch(0);

    for (int c = 0; c < NCHUNK; c++) {
        const int s = c & 1;
        if (c + 1 < NCHUNK) {
            prefetch(c + 1);
            CP_WAIT(1);
        } else {
            CP_WAIT(0);
        }
        __syncthreads();
#pragma unroll
        for (int ks = 0; ks < GBK; ks += 16) {
            wmma::fragment<wmma::matrix_b, 16, 16, 16, __nv_bfloat16, wmma::row_major> bf[4];
#pragma unroll
            for (int j = 0; j < 4; j++)
                wmma::load_matrix_sync(bf[j], Bs[s] + ks * B_LD + wn * 64 + j * 16, B_LD);
#pragma unroll
            for (int i = 0; i < 4; i++) {
                wmma::fragment<wmma::matrix_a, 16, 16, 16, __nv_bfloat16, wmma::row_major> af;
                wmma::load_matrix_sync(af, As[s] + (wm * 64 + i * 16) * A_LD + ks, A_LD);
#pragma unroll
                for (int j = 0; j < 4; j++)
                    wmma::mma_sync(acc[i][j], af, bf[j], acc[i][j]);
            }
        }
        __syncthreads();  // all warps done with buffer s before it is overwritten
    }

#pragma unroll
    for (int i = 0; i < 4; i++)
#pragma unroll
        for (int j = 0; j < 4; j++)
            wmma::store_matrix_sync(
                &C[(rowBase + wm * 64 + i * 16) * DIM + wn * 64 + j * 16],
                acc[i][j], DIM, wmma::mem_row_major);
}

// ---------------- graph preprocessing ------------------------------------------
__global__ void convert_batch_kernel(const void* batch) {
    int i = blockIdx.x * blockDim.x + threadIdx.x;
    if (i >= N_NODES) return;
    g_cnt[i] = 0;
    if (i <= N_GRAPHS) g_gstart[i] = N_NODES;
    int b = g_b_is64 ? (int)((const long long*)batch)[i] : ((const int*)batch)[i];
    b = min(max(b, 0), N_GRAPHS - 1);
    atomicMin(&g_gstart[b], i);
}

__global__ void convert_edges_kernel(const void* ei) {
    int e = blockIdx.x * blockDim.x + threadIdx.x;
    if (e >= N_EDGES) return;
    int s, d;
    if (g_ei_is64) {
        s = (int)((const long long*)ei)[e];
        d = (int)((const long long*)ei)[N_EDGES + e];
    } else {
        s = ((const int*)ei)[e];
        d = ((const int*)ei)[N_EDGES + e];
    }
    s = min(max(s, 0), N_NODES - 1);
    d = min(max(d, 0), N_NODES - 1);
    g_src32[e] = s;
    g_dst32[e] = d;
    atomicAdd(&g_cnt[d], 1);
}

__global__ __launch_bounds__(SCAN_BLK) void scan_pre() {
    const int t = threadIdx.x;
    int i = blockIdx.x * SCAN_BLK + t;
    int v = (i < N_NODES) ? g_cnt[i] : 0;
#pragma unroll
    for (int o = 16; o; o >>= 1) v += __shfl_xor_sync(0xffffffffu, v, o);
    __shared__ int ws[8];
    if ((t & 31) == 0) ws[t >> 5] = v;
    __syncthreads();
    if (t < 8) {
        int s = ws[t];
#pragma unroll
        for (int o = 4; o; o >>= 1) s += __shfl_xor_sync(0xffu, s, o);
        if (t == 0) g_bsum[blockIdx.x] = s;
    }
}

__global__ void scan_mid() {
    const int t = threadIdx.x;  // 128
    __shared__ int s[128];
    int v = (t < N_SCANB) ? g_bsum[t] : 0;
    s[t] = v;
    __syncthreads();
    for (int o = 1; o < 128; o <<= 1) {
        int u = (t >= o) ? s[t - o] : 0;
        __syncthreads();
        s[t] += u;
        __syncthreads();
    }
    if (t < N_SCANB) g_bbase[t] = s[t] - v;
    if (t == 0) g_off[N_NODES] = s[N_SCANB - 1];
    if (t == 64) {
        g_gstart[N_GRAPHS] = N_NODES;
        for (int g = N_GRAPHS - 1; g >= 0; g--)
            g_gstart[g] = min(g_gstart[g], g_gstart[g + 1]);
    }
}

__global__ __launch_bounds__(SCAN_BLK) void scan_post() {
    const int t = threadIdx.x;
    int i = blockIdx.x * SCAN_BLK + t;
    int c = (i < N_NODES) ? g_cnt[i] : 0;
    int v = c;
#pragma unroll
    for (int o = 1; o < 32; o <<= 1) {
        int u = __shfl_up_sync(0xffffffffu, v, o);
        if ((t & 31) >= o) v += u;
    }
    __shared__ int ws[8];
    if ((t & 31) == 31) ws[t >> 5] = v;
    __syncthreads();
    if (t < 8) {
        int s = ws[t];
#pragma unroll
        for (int o = 1; o < 8; o <<= 1) {
            int u = __shfl_up_sync(0xffu, s, o);
            if (t >= o) s += u;
        }
        ws[t] = s;
    }
    __syncthreads();
    int warpBase = (t >= 32) ? ws[(t >> 5) - 1] : 0;
    int excl = g_bbase[blockIdx.x] + warpBase + v - c;
    if (i < N_NODES) {
        g_off[i] = excl;
        g_cur[i] = excl;
        g_dinv[i] = rsqrtf((float)c + 1.0f);
    }
}

__global__ void fill_kernel() {
    int e = blockIdx.x * blockDim.x + threadIdx.x;
    if (e < N_EDGES) {
        int s = g_src32[e];
        int d = g_dst32[e];
        int p = atomicAdd(&g_cur[d], 1);
        if (p >= 0 && p < N_EDGES) {
            g_csr[p] = s;
            g_w[p] = g_dinv[s] * g_dinv[d];
        }
    }
}

// ---------------- aggregation (+ fused bf16 hi/lo output for next GEMM) --------
// MODE 0: relu(agg + b) | MODE 1: relu(resid + agg + b) | MODE 2: agg + b
template <int MODE, int WRITE_BF>
__global__ __launch_bounds__(256) void agg_kernel(
    const float4* __restrict__ T4, const float4* __restrict__ bias4,
    const float4* __restrict__ resid4, float4* __restrict__ out4) {
    const int i = blockIdx.x;
    const int tid = threadIdx.x;
    const int d4 = tid & 63;
    const int eg = tid >> 6;
    const int e0 = g_off[i], e1 = g_off[i + 1];

    float4 a0 = make_float4(0.f, 0.f, 0.f, 0.f);
    float4 a1 = a0;
    int e = e0 + eg;
    for (; e + 4 < e1; e += 8) {
        int s0 = g_csr[e];
        float w0 = g_w[e];
        int s1 = g_csr[e + 4];
        float w1 = g_w[e + 4];
        float4 v0 = T4[s0 * 64 + d4];
        float4 v1 = T4[s1 * 64 + d4];
        a0.x = fmaf(w0, v0.x, a0.x); a0.y = fmaf(w0, v0.y, a0.y);
        a0.z = fmaf(w0, v0.z, a0.z); a0.w = fmaf(w0, v0.w, a0.w);
        a1.x = fmaf(w1, v1.x, a1.x); a1.y = fmaf(w1, v1.y, a1.y);
        a1.z = fmaf(w1, v1.z, a1.z); a1.w = fmaf(w1, v1.w, a1.w);
    }
    if (e < e1) {
        int s = g_csr[e];
        float w = g_w[e];
        float4 v = T4[s * 64 + d4];
        a0.x = fmaf(w, v.x, a0.x); a0.y = fmaf(w, v.y, a0.y);
        a0.z = fmaf(w, v.z, a0.z); a0.w = fmaf(w, v.w, a0.w);
    }
    a0.x += a1.x; a0.y += a1.y; a0.z += a1.z; a0.w += a1.w;

    __shared__ float4 part[3][64];
    if (eg > 0) part[eg - 1][d4] = a0;
    __syncthreads();
    if (eg == 0) {
        const float di = g_dinv[i];
        float4 self = T4[i * 64 + d4];
        float dii = di * di;
        float4 b = bias4[d4];
        float4 acc;
        acc.x = a0.x + part[0][d4].x + part[1][d4].x + part[2][d4].x + self.x * dii + b.x;
        acc.y = a0.y + part[0][d4].y + part[1][d4].y + part[2][d4].y + self.y * dii + b.y;
        acc.z = a0.z + part[0][d4].z + part[1][d4].z + part[2][d4].z + self.z * dii + b.z;
        acc.w = a0.w + part[0][d4].w + part[1][d4].w + part[2][d4].w + self.w * dii + b.w;
        if (MODE == 1) {
            float4 r = resid4[i * 64 + d4];
            acc.x += r.x; acc.y += r.y; acc.z += r.z; acc.w += r.w;
        }
        if (MODE <= 1) {
            acc.x = fmaxf(acc.x, 0.f); acc.y = fmaxf(acc.y, 0.f);
            acc.z = fmaxf(acc.z, 0.f); acc.w = fmaxf(acc.w, 0.f);
        }
        out4[i * 64 + d4] = acc;
        if (WRITE_BF) {
            __nv_bfloat162 h0 = __floats2bfloat162_rn(acc.x, acc.y);
            __nv_bfloat162 h1 = __floats2bfloat162_rn(acc.z, acc.w);
            float l0 = acc.x - __low2float(h0);
            float l1 = acc.y - __high2float(h0);
            float l2 = acc.z - __low2float(h1);
            float l3 = acc.w - __high2float(h1);
            int base = i * 128 + d4 * 2;
            ((__nv_bfloat162*)g_Ahi)[base]     = h0;
            ((__nv_bfloat162*)g_Ahi)[base + 1] = h1;
            ((__nv_bfloat162*)g_Alo)[base]     = __floats2bfloat162_rn(l0, l1);
            ((__nv_bfloat162*)g_Alo)[base + 1] = __floats2bfloat162_rn(l2, l3);
        }
    }
}

// ---------------- pooling ------------------------------------------------------
__global__ __launch_bounds__(256) void pool_kernel(const float4* __restrict__ h4) {
    const int g = blockIdx.x;
    const int tid = threadIdx.x;
    const int d4 = tid & 63;
    const int rg = tid >> 6;
    const int r0 = g_gstart[g], r1 = g_gstart[g + 1];
    float4 acc = make_float4(0.f, 0.f, 0.f, 0.f);
    for (int i = r0 + rg; i < r1; i += 4) {
        float4 v = h4[i * 64 + d4];
        acc.x += v.x; acc.y += v.y; acc.z += v.z; acc.w += v.w;
    }
    __shared__ float4 part[4][64];
    part[rg][d4] = acc;
    __syncthreads();
    if (rg == 0) {
        float inv = 1.0f / fmaxf((float)(r1 - r0), 1.0f);
        float4 s;
        s.x = (part[0][d4].x + part[1][d4].x + part[2][d4].x + part[3][d4].x) * inv;
        s.y = (part[0][d4].y + part[1][d4].y + part[2][d4].y + part[3][d4].y) * inv;
        s.z = (part[0][d4].z + part[1][d4].z + part[2][d4].z + part[3][d4].z) * inv;
        s.w = (part[0][d4].w + part[1][d4].w + part[2][d4].w + part[3][d4].w) * inv;
        reinterpret_cast<float4*>(g_pool)[g * 64 + d4] = s;
    }
}

// ---------------- classifier + log_softmax -------------------------------------
__global__ __launch_bounds__(256) void cls_kernel(const float* __restrict__ Wc,
                                                  const float* __restrict__ bc,
                                                  float* __restrict__ out,
                                                  int out_size) {
    const int g = blockIdx.x;
    const int t = threadIdx.x;
    __shared__ float p[DIM];
    __shared__ float logits[N_CLASSES];
    p[t] = g_pool[g * DIM + t];
    __syncthreads();
    const int w = t >> 5, lane = t & 31;
    for (int cls = w; cls < N_CLASSES; cls += 8) {
        float s = 0.0f;
        for (int k = lane; k < DIM; k += 32) s += p[k] * Wc[k * N_CLASSES + cls];
#pragma unroll
        for (int o = 16; o; o >>= 1) s += __shfl_xor_sync(0xffffffffu, s, o);
        if (lane == 0) logits[cls] = s + bc[cls];
    }
    __syncthreads();
    if (t < N_CLASSES) {
        float mx = -1e30f;
#pragma unroll
        for (int k = 0; k < N_CLASSES; k++) mx = fmaxf(mx, logits[k]);
        float sum = 0.0f;
#pragma unroll
        for (int k = 0; k < N_CLASSES; k++) sum += expf(logits[k] - mx);
        float lse = mx + logf(sum);
        out[g * N_CLASSES + t] = logits[t];
        if (out_size >= 2 * N_GRAPHS * N_CLASSES)
            out[N_GRAPHS * N_CLASSES + g * N_CLASSES + t] = logits[t] - lse;
    }
}

// ---------------- launch ---------------------------------------------------------
extern "C" void kernel_launch(void* const* d_in, const int* in_sizes, int n_in,
                              void* d_out, int out_size) {
    const float* x = (const float*)d_in[0];
    const void*  ei = d_in[1];
    const void*  batch = d_in[2];
    const float* W1 = (const float*)d_in[3];
    const float* b1 = (const float*)d_in[4];
    const float* W2 = (const float*)d_in[5];
    const float* b2 = (const float*)d_in[6];
    const float* W3 = (const float*)d_in[7];
    const float* b3 = (const float*)d_in[8];
    const float* Wc = (const float*)d_in[9];
    const float* bc = (const float*)d_in[10];
    float* out = (float*)d_out;

    float* T; float* A; float* B;
    cudaGetSymbolAddress((void**)&T, g_T);
    cudaGetSymbolAddress((void**)&A, g_A);
    cudaGetSymbolAddress((void**)&B, g_B);

    static int smem_set = 0;
    if (!smem_set) {
        cudaFuncSetAttribute(gemm_wmma, cudaFuncAttributeMaxDynamicSharedMemorySize,
                             GEMM_SMEM);
        smem_set = 1;
    }

    const int CONV_GRID = (PAD_M * 64 + 255) / 256;
    const int ggrid = PAD_M / GBM;  // 157

    // idx 0-2
    detect_kernel<<<1, 1024>>>(ei, batch);
    convert_in<<<CONV_GRID, 256>>>((const float4*)x);
    convert_w<<<(3 * DIM * DIM + 255) / 256, 256>>>(W1, W2, W3);
    // idx 3: layer-1 GEMM — profiled slot
    gemm_wmma<<<ggrid, 256, GEMM_SMEM>>>(0, T);
    // graph preprocessing
    convert_batch_kernel<<<(N_NODES + 255) / 256, 256>>>(batch);
    convert_edges_kernel<<<(N_EDGES + 255) / 256, 256>>>(ei);
    scan_pre<<<N_SCANB, SCAN_BLK>>>();
    scan_mid<<<1, 128>>>();
    scan_post<<<N_SCANB, SCAN_BLK>>>();
    fill_kernel<<<(N_EDGES + 255) / 256, 256>>>();
    // layer 1 aggregate (writes bf16 hi/lo for layer-2 GEMM)
    agg_kernel<0, 1><<<N_NODES, 256>>>((const float4*)T, (const float4*)b1, nullptr,
                                       (float4*)A);
    // layer 2
    gemm_wmma<<<ggrid, 256, GEMM_SMEM>>>(1, T);
    agg_kernel<1, 1><<<N_NODES, 256>>>((const float4*)T, (const float4*)b2,
                                       (const float4*)A, (float4*)B);
    // layer 3
    gemm_wmma<<<ggrid, 256, GEMM_SMEM>>>(2, T);
    agg_kernel<2, 0><<<N_NODES, 256>>>((const float4*)T, (const float4*)b3, nullptr,
                                       (float4*)A);

    pool_kernel<<<N_GRAPHS, 256>>>((const float4*)A);
    cls_kernel<<<N_GRAPHS, 256>>>(Wc, bc, out, out_size);
}

// round 9
// speedup vs baseline: 1.5677x; 1.0837x over previous
#include <cuda_runtime.h>
#include <cuda_bf16.h>
#include <mma.h>
#include <math.h>
#include <stdint.h>

using namespace nvcuda;

// ---------------------------------------------------------------------------
// GCN_9062380994846: 3-layer GCN + mean pool + classifier + log_softmax
// GEMMs: WMMA bf16 hi/lo split (K'=768). Preprocessing overlapped on a
// side stream inside the captured graph.
// ---------------------------------------------------------------------------

#define N_NODES   20000
#define N_EDGES   320000
#define DIM       256
#define N_GRAPHS  64
#define N_CLASSES 10
#define SCAN_BLK  256
#define N_SCANB   ((N_NODES + SCAN_BLK - 1) / SCAN_BLK)   // 79
#define PAD_M     20096                                    // 157 * 128
#define KP        768

// ---------------- scratch ----------------------------------------------------
__device__ float g_T[PAD_M * DIM];
__device__ float g_A[PAD_M * DIM];
__device__ float g_B[PAD_M * DIM];
__device__ __nv_bfloat16 g_Ahi[PAD_M * DIM];
__device__ __nv_bfloat16 g_Alo[PAD_M * DIM];
__device__ __nv_bfloat16 g_Bext[3 * KP * DIM];   // [layer][768][256]: hi;lo;hi
__device__ int   g_src32[N_EDGES];
__device__ int   g_dst32[N_EDGES];
__device__ int   g_cnt[N_NODES];        // zero-init at load; restored by fill_kernel
__device__ int   g_off[N_NODES + 1];
__device__ int   g_cur[N_NODES];
__device__ int   g_csr[N_EDGES];
__device__ float g_w[N_EDGES];
__device__ float g_dinv[N_NODES];
__device__ int   g_bsum[N_SCANB];
__device__ int   g_bbase[N_SCANB];
__device__ int   g_gstart[N_GRAPHS + 1];
__device__ int   g_ei_is64;
__device__ int   g_b_is64;

// ---------------- host-side aux (created at static init, reused forever) ------
static cudaStream_t g_side = nullptr;
static cudaEvent_t  g_evf = nullptr, g_evj = nullptr;
struct AuxInit {
    AuxInit() {
        cudaStreamCreateWithFlags(&g_side, cudaStreamNonBlocking);
        cudaEventCreateWithFlags(&g_evf, cudaEventDisableTiming);
        cudaEventCreateWithFlags(&g_evj, cudaEventDisableTiming);
    }
};
static AuxInit g_auxinit;

// ---------------- cp.async helpers ---------------------------------------------
__device__ __forceinline__ void cpa16(uint32_t dst, const void* src) {
    asm volatile("cp.async.cg.shared.global [%0], [%1], 16;" :: "r"(dst), "l"(src));
}
#define CP_COMMIT() asm volatile("cp.async.commit_group;" ::: "memory")
#define CP_WAIT(N)  asm volatile("cp.async.wait_group %0;" :: "n"(N) : "memory")

// ---------------- dtype detection + gstart seeding ------------------------------
__global__ void detect_kernel(const void* ei, const void* batch) {
    int t = threadIdx.x;  // 1024 threads
    if (t == 0) { g_ei_is64 = 1; g_b_is64 = 1; }
    if (t <= N_GRAPHS) g_gstart[t] = N_NODES;
    __syncthreads();
    long long v = ((const long long*)ei)[(long long)t * 312];
    if (v < 0 || v >= N_NODES) atomicExch(&g_ei_is64, 0);
    long long b = ((const long long*)batch)[t * 9];
    if (b < 0 || b >= N_GRAPHS) atomicExch(&g_b_is64, 0);
}

// ---------------- merged batch+edge conversion (g_cnt already zero) -------------
__global__ void convert_graph(const void* ei, const void* batch) {
    int i = blockIdx.x * blockDim.x + threadIdx.x;
    if (i < N_NODES) {
        int b = g_b_is64 ? (int)((const long long*)batch)[i] : ((const int*)batch)[i];
        b = min(max(b, 0), N_GRAPHS - 1);
        atomicMin(&g_gstart[b], i);
    }
    if (i >= N_EDGES) return;
    int s, d;
    if (g_ei_is64) {
        s = (int)((const long long*)ei)[i];
        d = (int)((const long long*)ei)[N_EDGES + i];
    } else {
        s = ((const int*)ei)[i];
        d = ((const int*)ei)[N_EDGES + i];
    }
    s = min(max(s, 0), N_NODES - 1);
    d = min(max(d, 0), N_NODES - 1);
    g_src32[i] = s;
    g_dst32[i] = d;
    atomicAdd(&g_cnt[d], 1);
}

// ---------------- fp32 -> bf16 hi/lo ---------------------------------------------
__global__ __launch_bounds__(256) void convert_in(const float4* __restrict__ src) {
    int i = blockIdx.x * 256 + threadIdx.x;
    if (i >= PAD_M * 64) return;
    int row = i >> 6;
    float4 v = make_float4(0.f, 0.f, 0.f, 0.f);
    if (row < N_NODES) v = src[i];
    __nv_bfloat162 h0 = __floats2bfloat162_rn(v.x, v.y);
    __nv_bfloat162 h1 = __floats2bfloat162_rn(v.z, v.w);
    float l0 = v.x - __low2float(h0);
    float l1 = v.y - __high2float(h0);
    float l2 = v.z - __low2float(h1);
    float l3 = v.w - __high2float(h1);
    ((__nv_bfloat162*)g_Ahi)[2 * i]     = h0;
    ((__nv_bfloat162*)g_Ahi)[2 * i + 1] = h1;
    ((__nv_bfloat162*)g_Alo)[2 * i]     = __floats2bfloat162_rn(l0, l1);
    ((__nv_bfloat162*)g_Alo)[2 * i + 1] = __floats2bfloat162_rn(l2, l3);
}

__global__ __launch_bounds__(256) void convert_w(const float* __restrict__ W1,
                                                 const float* __restrict__ W2,
                                                 const float* __restrict__ W3) {
    int i = blockIdx.x * 256 + threadIdx.x;
    if (i >= 3 * DIM * DIM) return;
    int w = i >> 16, r = i & 0xFFFF;
    int k = r >> 8, n = r & 255;
    const float* W = (w == 0) ? W1 : (w == 1) ? W2 : W3;
    float v = W[k * DIM + n];
    __nv_bfloat16 h = __float2bfloat16(v);
    __nv_bfloat16 l = __float2bfloat16(v - __bfloat162float(h));
    __nv_bfloat16* Be = g_Bext + w * KP * DIM;
    Be[k * DIM + n] = h;
    Be[(256 + k) * DIM + n] = l;
    Be[(512 + k) * DIM + n] = h;
}

// ---------------- WMMA GEMM (unchanged from R8: legacy-HMMA near-floor) ---------
#define GBM 128
#define GBN 256
#define GBK 64
#define NCHUNK (KP / GBK)         // 12
#define A_LD  (GBK + 8)
#define B_LD  (GBN + 8)
#define A_SZ  (GBM * A_LD * 2)
#define B_SZ  (GBK * B_LD * 2)
#define GEMM_SMEM (2 * (A_SZ + B_SZ))

__global__ __launch_bounds__(256, 1) void gemm_wmma(int layer, float* __restrict__ C) {
    extern __shared__ __align__(16) char smem[];
    const int tid = threadIdx.x;
    const int wid = tid >> 5;
    const int wm = wid & 1;
    const int wn = wid >> 1;
    const int rowBase = blockIdx.x * GBM;
    const __nv_bfloat16* Bext = g_Bext + layer * KP * DIM;

    __nv_bfloat16* As[2] = {(__nv_bfloat16*)smem, (__nv_bfloat16*)(smem + A_SZ)};
    __nv_bfloat16* Bs[2] = {(__nv_bfloat16*)(smem + 2 * A_SZ),
                            (__nv_bfloat16*)(smem + 2 * A_SZ + B_SZ)};

    auto prefetch = [&](int c) {
        const int s = c & 1;
        const __nv_bfloat16* Ap = (c < 8) ? g_Ahi : g_Alo;
        const int ko = (c & 3) * GBK;
        uint32_t abase = (uint32_t)__cvta_generic_to_shared(As[s]);
#pragma unroll
        for (int t = 0; t < 4; t++) {
            int q = tid + t * 256;
            int row = q >> 3, seg = q & 7;
            cpa16(abase + (row * A_LD + seg * 8) * 2,
                  Ap + (rowBase + row) * DIM + ko + seg * 8);
        }
        uint32_t bbase = (uint32_t)__cvta_generic_to_shared(Bs[s]);
#pragma unroll
        for (int t = 0; t < 8; t++) {
            int q = tid + t * 256;
            int row = q >> 5, seg = q & 31;
            cpa16(bbase + (row * B_LD + seg * 8) * 2,
                  Bext + (c * GBK + row) * DIM + seg * 8);
        }
        CP_COMMIT();
    };

    wmma::fragment<wmma::accumulator, 16, 16, 16, float> acc[4][4];
#pragma unroll
    for (int i = 0; i < 4; i++)
#pragma unroll
        for (int j = 0; j < 4; j++) wmma::fill_fragment(acc[i][j], 0.0f);

    prefetch(0);

    for (int c = 0; c < NCHUNK; c++) {
        const int s = c & 1;
        if (c + 1 < NCHUNK) {
            prefetch(c + 1);
            CP_WAIT(1);
        } else {
            CP_WAIT(0);
        }
        __syncthreads();
#pragma unroll
        for (int ks = 0; ks < GBK; ks += 16) {
            wmma::fragment<wmma::matrix_b, 16, 16, 16, __nv_bfloat16, wmma::row_major> bf[4];
#pragma unroll
            for (int j = 0; j < 4; j++)
                wmma::load_matrix_sync(bf[j], Bs[s] + ks * B_LD + wn * 64 + j * 16, B_LD);
#pragma unroll
            for (int i = 0; i < 4; i++) {
                wmma::fragment<wmma::matrix_a, 16, 16, 16, __nv_bfloat16, wmma::row_major> af;
                wmma::load_matrix_sync(af, As[s] + (wm * 64 + i * 16) * A_LD + ks, A_LD);
#pragma unroll
                for (int j = 0; j < 4; j++)
                    wmma::mma_sync(acc[i][j], af, bf[j], acc[i][j]);
            }
        }
        __syncthreads();
    }

#pragma unroll
    for (int i = 0; i < 4; i++)
#pragma unroll
        for (int j = 0; j < 4; j++)
            wmma::store_matrix_sync(
                &C[(rowBase + wm * 64 + i * 16) * DIM + wn * 64 + j * 16],
                acc[i][j], DIM, wmma::mem_row_major);
}

// ---------------- 3-phase scan ---------------------------------------------------
__global__ __launch_bounds__(SCAN_BLK) void scan_pre() {
    const int t = threadIdx.x;
    int i = blockIdx.x * SCAN_BLK + t;
    int v = (i < N_NODES) ? g_cnt[i] : 0;
#pragma unroll
    for (int o = 16; o; o >>= 1) v += __shfl_xor_sync(0xffffffffu, v, o);
    __shared__ int ws[8];
    if ((t & 31) == 0) ws[t >> 5] = v;
    __syncthreads();
    if (t < 8) {
        int s = ws[t];
#pragma unroll
        for (int o = 4; o; o >>= 1) s += __shfl_xor_sync(0xffu, s, o);
        if (t == 0) g_bsum[blockIdx.x] = s;
    }
}

__global__ void scan_mid() {
    const int t = threadIdx.x;  // 128
    __shared__ int s[128];
    int v = (t < N_SCANB) ? g_bsum[t] : 0;
    s[t] = v;
    __syncthreads();
    for (int o = 1; o < 128; o <<= 1) {
        int u = (t >= o) ? s[t - o] : 0;
        __syncthreads();
        s[t] += u;
        __syncthreads();
    }
    if (t < N_SCANB) g_bbase[t] = s[t] - v;
    if (t == 0) g_off[N_NODES] = s[N_SCANB - 1];
    if (t == 64) {
        g_gstart[N_GRAPHS] = N_NODES;
        for (int g = N_GRAPHS - 1; g >= 0; g--)
            g_gstart[g] = min(g_gstart[g], g_gstart[g + 1]);
    }
}

__global__ __launch_bounds__(SCAN_BLK) void scan_post() {
    const int t = threadIdx.x;
    int i = blockIdx.x * SCAN_BLK + t;
    int c = (i < N_NODES) ? g_cnt[i] : 0;
    int v = c;
#pragma unroll
    for (int o = 1; o < 32; o <<= 1) {
        int u = __shfl_up_sync(0xffffffffu, v, o);
        if ((t & 31) >= o) v += u;
    }
    __shared__ int ws[8];
    if ((t & 31) == 31) ws[t >> 5] = v;
    __syncthreads();
    if (t < 8) {
        int s = ws[t];
#pragma unroll
        for (int o = 1; o < 8; o <<= 1) {
            int u = __shfl_up_sync(0xffu, s, o);
            if (t >= o) s += u;
        }
        ws[t] = s;
    }
    __syncthreads();
    int warpBase = (t >= 32) ? ws[(t >> 5) - 1] : 0;
    int excl = g_bbase[blockIdx.x] + warpBase + v - c;
    if (i < N_NODES) {
        g_off[i] = excl;
        g_cur[i] = excl;
        g_dinv[i] = rsqrtf((float)c + 1.0f);
    }
}

// CSR fill + edge weight; also restores g_cnt = 0 for the next call
__global__ void fill_kernel() {
    int e = blockIdx.x * blockDim.x + threadIdx.x;
    if (e < N_NODES) g_cnt[e] = 0;   // scan_post was the last reader
    if (e < N_EDGES) {
        int s = g_src32[e];
        int d = g_dst32[e];
        int p = atomicAdd(&g_cur[d], 1);
        if (p >= 0 && p < N_EDGES) {
            g_csr[p] = s;
            g_w[p] = g_dinv[s] * g_dinv[d];
        }
    }
}

// ---------------- aggregation (+ fused bf16 hi/lo output for next GEMM) ---------
template <int MODE, int WRITE_BF>
__global__ __launch_bounds__(256) void agg_kernel(
    const float4* __restrict__ T4, const float4* __restrict__ bias4,
    const float4* __restrict__ resid4, float4* __restrict__ out4) {
    const int i = blockIdx.x;
    const int tid = threadIdx.x;
    const int d4 = tid & 63;
    const int eg = tid >> 6;
    const int e0 = g_off[i], e1 = g_off[i + 1];

    float4 a0 = make_float4(0.f, 0.f, 0.f, 0.f);
    float4 a1 = a0;
    int e = e0 + eg;
    for (; e + 4 < e1; e += 8) {
        int s0 = g_csr[e];
        float w0 = g_w[e];
        int s1 = g_csr[e + 4];
        float w1 = g_w[e + 4];
        float4 v0 = T4[s0 * 64 + d4];
        float4 v1 = T4[s1 * 64 + d4];
        a0.x = fmaf(w0, v0.x, a0.x); a0.y = fmaf(w0, v0.y, a0.y);
        a0.z = fmaf(w0, v0.z, a0.z); a0.w = fmaf(w0, v0.w, a0.w);
        a1.x = fmaf(w1, v1.x, a1.x); a1.y = fmaf(w1, v1.y, a1.y);
        a1.z = fmaf(w1, v1.z, a1.z); a1.w = fmaf(w1, v1.w, a1.w);
    }
    if (e < e1) {
        int s = g_csr[e];
        float w = g_w[e];
        float4 v = T4[s * 64 + d4];
        a0.x = fmaf(w, v.x, a0.x); a0.y = fmaf(w, v.y, a0.y);
        a0.z = fmaf(w, v.z, a0.z); a0.w = fmaf(w, v.w, a0.w);
    }
    a0.x += a1.x; a0.y += a1.y; a0.z += a1.z; a0.w += a1.w;

    __shared__ float4 part[3][64];
    if (eg > 0) part[eg - 1][d4] = a0;
    __syncthreads();
    if (eg == 0) {
        const float di = g_dinv[i];
        float4 self = T4[i * 64 + d4];
        float dii = di * di;
        float4 b = bias4[d4];
        float4 acc;
        acc.x = a0.x + part[0][d4].x + part[1][d4].x + part[2][d4].x + self.x * dii + b.x;
        acc.y = a0.y + part[0][d4].y + part[1][d4].y + part[2][d4].y + self.y * dii + b.y;
        acc.z = a0.z + part[0][d4].z + part[1][d4].z + part[2][d4].z + self.z * dii + b.z;
        acc.w = a0.w + part[0][d4].w + part[1][d4].w + part[2][d4].w + self.w * dii + b.w;
        if (MODE == 1) {
            float4 r = resid4[i * 64 + d4];
            acc.x += r.x; acc.y += r.y; acc.z += r.z; acc.w += r.w;
        }
        if (MODE <= 1) {
            acc.x = fmaxf(acc.x, 0.f); acc.y = fmaxf(acc.y, 0.f);
            acc.z = fmaxf(acc.z, 0.f); acc.w = fmaxf(acc.w, 0.f);
        }
        out4[i * 64 + d4] = acc;
        if (WRITE_BF) {
            __nv_bfloat162 h0 = __floats2bfloat162_rn(acc.x, acc.y);
            __nv_bfloat162 h1 = __floats2bfloat162_rn(acc.z, acc.w);
            float l0 = acc.x - __low2float(h0);
            float l1 = acc.y - __high2float(h0);
            float l2 = acc.z - __low2float(h1);
            float l3 = acc.w - __high2float(h1);
            int base = i * 128 + d4 * 2;
            ((__nv_bfloat162*)g_Ahi)[base]     = h0;
            ((__nv_bfloat162*)g_Ahi)[base + 1] = h1;
            ((__nv_bfloat162*)g_Alo)[base]     = __floats2bfloat162_rn(l0, l1);
            ((__nv_bfloat162*)g_Alo)[base + 1] = __floats2bfloat162_rn(l2, l3);
        }
    }
}

// ---------------- merged pooling + classifier + log_softmax ----------------------
__global__ __launch_bounds__(256) void pool_cls(const float4* __restrict__ h4,
                                                const float* __restrict__ Wc,
                                                const float* __restrict__ bc,
                                                float* __restrict__ out,
                                                int out_size) {
    const int g = blockIdx.x;
    const int tid = threadIdx.x;
    const int d4 = tid & 63;
    const int rg = tid >> 6;
    const int r0 = g_gstart[g], r1 = g_gstart[g + 1];
    float4 acc = make_float4(0.f, 0.f, 0.f, 0.f);
    for (int i = r0 + rg; i < r1; i += 4) {
        float4 v = h4[i * 64 + d4];
        acc.x += v.x; acc.y += v.y; acc.z += v.z; acc.w += v.w;
    }
    __shared__ float4 part[4][64];
    __shared__ float p[DIM];
    __shared__ float logits[N_CLASSES];
    part[rg][d4] = acc;
    __syncthreads();
    if (rg == 0) {
        float inv = 1.0f / fmaxf((float)(r1 - r0), 1.0f);
        p[d4 * 4 + 0] = (part[0][d4].x + part[1][d4].x + part[2][d4].x + part[3][d4].x) * inv;
        p[d4 * 4 + 1] = (part[0][d4].y + part[1][d4].y + part[2][d4].y + part[3][d4].y) * inv;
        p[d4 * 4 + 2] = (part[0][d4].z + part[1][d4].z + part[2][d4].z + part[3][d4].z) * inv;
        p[d4 * 4 + 3] = (part[0][d4].w + part[1][d4].w + part[2][d4].w + part[3][d4].w) * inv;
    }
    __syncthreads();
    const int w = tid >> 5, lane = tid & 31;
    for (int cls = w; cls < N_CLASSES; cls += 8) {
        float s = 0.0f;
        for (int k = lane; k < DIM; k += 32) s += p[k] * Wc[k * N_CLASSES + cls];
#pragma unroll
        for (int o = 16; o; o >>= 1) s += __shfl_xor_sync(0xffffffffu, s, o);
        if (lane == 0) logits[cls] = s + bc[cls];
    }
    __syncthreads();
    if (tid < N_CLASSES) {
        float mx = -1e30f;
#pragma unroll
        for (int k = 0; k < N_CLASSES; k++) mx = fmaxf(mx, logits[k]);
        float sum = 0.0f;
#pragma unroll
        for (int k = 0; k < N_CLASSES; k++) sum += expf(logits[k] - mx);
        float lse = mx + logf(sum);
        out[g * N_CLASSES + tid] = logits[tid];
        if (out_size >= 2 * N_GRAPHS * N_CLASSES)
            out[N_GRAPHS * N_CLASSES + g * N_CLASSES + tid] = logits[tid] - lse;
    }
}

// ---------------- launch ----------------------------------------------------------
extern "C" void kernel_launch(void* const* d_in, const int* in_sizes, int n_in,
                              void* d_out, int out_size) {
    const float* x = (const float*)d_in[0];
    const void*  ei = d_in[1];
    const void*  batch = d_in[2];
    const float* W1 = (const float*)d_in[3];
    const float* b1 = (const float*)d_in[4];
    const float* W2 = (const float*)d_in[5];
    const float* b2 = (const float*)d_in[6];
    const float* W3 = (const float*)d_in[7];
    const float* b3 = (const float*)d_in[8];
    const float* Wc = (const float*)d_in[9];
    const float* bc = (const float*)d_in[10];
    float* out = (float*)d_out;

    float* T; float* A; float* B;
    cudaGetSymbolAddress((void**)&T, g_T);
    cudaGetSymbolAddress((void**)&A, g_A);
    cudaGetSymbolAddress((void**)&B, g_B);

    static int smem_set = 0;
    if (!smem_set) {
        cudaFuncSetAttribute(gemm_wmma, cudaFuncAttributeMaxDynamicSharedMemorySize,
                             GEMM_SMEM);
        smem_set = 1;
    }

    const int CONV_GRID = (PAD_M * 64 + 255) / 256;
    const int EDGE_GRID = (N_EDGES + 255) / 256;
    const int ggrid = PAD_M / GBM;  // 157

    const bool use_side = (g_side != nullptr && g_evf != nullptr && g_evj != nullptr);

    // head: dtype detect (needed by side chain)
    detect_kernel<<<1, 1024>>>(ei, batch);

    if (use_side) {
        cudaEventRecord(g_evf, 0);
        cudaStreamWaitEvent(g_side, g_evf, 0);
        // side stream: graph preprocessing (hidden under converts + gemm1)
        convert_graph<<<EDGE_GRID, 256, 0, g_side>>>(ei, batch);
        scan_pre<<<N_SCANB, SCAN_BLK, 0, g_side>>>();
        scan_mid<<<1, 128, 0, g_side>>>();
        scan_post<<<N_SCANB, SCAN_BLK, 0, g_side>>>();
        fill_kernel<<<EDGE_GRID, 256, 0, g_side>>>();
        cudaEventRecord(g_evj, g_side);
    } else {
        convert_graph<<<EDGE_GRID, 256>>>(ei, batch);
        scan_pre<<<N_SCANB, SCAN_BLK>>>();
        scan_mid<<<1, 128>>>();
        scan_post<<<N_SCANB, SCAN_BLK>>>();
        fill_kernel<<<EDGE_GRID, 256>>>();
    }

    // main stream: converts + layer-1 GEMM
    convert_in<<<CONV_GRID, 256>>>((const float4*)x);
    convert_w<<<(3 * DIM * DIM + 255) / 256, 256>>>(W1, W2, W3);
    gemm_wmma<<<ggrid, 256, GEMM_SMEM>>>(0, T);

    if (use_side) cudaStreamWaitEvent(0, g_evj, 0);   // join before agg1

    // layer 1 aggregate (writes bf16 hi/lo for layer-2 GEMM)
    agg_kernel<0, 1><<<N_NODES, 256>>>((const float4*)T, (const float4*)b1, nullptr,
                                       (float4*)A);
    // layer 2
    gemm_wmma<<<ggrid, 256, GEMM_SMEM>>>(1, T);
    agg_kernel<1, 1><<<N_NODES, 256>>>((const float4*)T, (const float4*)b2,
                                       (const float4*)A, (float4*)B);
    // layer 3
    gemm_wmma<<<ggrid, 256, GEMM_SMEM>>>(2, T);
    agg_kernel<2, 0><<<N_NODES, 256>>>((const float4*)T, (const float4*)b3, nullptr,
                                       (float4*)A);

    // merged pooling + classifier
    pool_cls<<<N_GRAPHS, 256>>>((const float4*)A, Wc, bc, out, out_size);
}

// round 10
// speedup vs baseline: 1.9589x; 1.2496x over previous
#include <cuda_runtime.h>
#include <cuda_bf16.h>
#include <mma.h>
#include <math.h>
#include <stdint.h>

using namespace nvcuda;

// ---------------------------------------------------------------------------
// GCN_9062380994846: 3-layer GCN + mean pool + classifier + log_softmax
// GEMMs: WMMA bf16 hi/lo split (K'=768), single-wave grid (139 CTAs, BM=144)
// ---------------------------------------------------------------------------

#define N_NODES   20000
#define N_EDGES   320000
#define DIM       256
#define N_GRAPHS  64
#define N_CLASSES 10
#define SCAN_BLK  256
#define N_SCANB   ((N_NODES + SCAN_BLK - 1) / SCAN_BLK)   // 79
#define PAD_M     20016                                    // 139 * 144
#define KP        768

// ---------------- scratch ----------------------------------------------------
__device__ float g_T[PAD_M * DIM];
__device__ float g_A[PAD_M * DIM];
__device__ float g_B[PAD_M * DIM];
__device__ __nv_bfloat16 g_Ahi[PAD_M * DIM];
__device__ __nv_bfloat16 g_Alo[PAD_M * DIM];
__device__ __nv_bfloat16 g_Bext[3 * KP * DIM];   // [layer][768][256]: hi;lo;hi
__device__ int   g_src32[N_EDGES];
__device__ int   g_dst32[N_EDGES];
__device__ int   g_cnt[N_NODES];        // zero-init at load; restored by fill_kernel
__device__ int   g_off[N_NODES + 1];
__device__ int   g_cur[N_NODES];
__device__ int   g_csr[N_EDGES];
__device__ float g_w[N_EDGES];
__device__ float g_dinv[N_NODES];
__device__ int   g_bsum[N_SCANB];
__device__ int   g_bbase[N_SCANB];
__device__ int   g_gstart[N_GRAPHS + 1];
__device__ int   g_ei_is64;
__device__ int   g_b_is64;

// ---------------- host-side aux (created at static init, reused forever) ------
static cudaStream_t g_side = nullptr;
static cudaEvent_t  g_evf = nullptr, g_evj = nullptr;
struct AuxInit {
    AuxInit() {
        cudaStreamCreateWithFlags(&g_side, cudaStreamNonBlocking);
        cudaEventCreateWithFlags(&g_evf, cudaEventDisableTiming);
        cudaEventCreateWithFlags(&g_evj, cudaEventDisableTiming);
    }
};
static AuxInit g_auxinit;

// ---------------- cp.async helpers ---------------------------------------------
__device__ __forceinline__ void cpa16(uint32_t dst, const void* src) {
    asm volatile("cp.async.cg.shared.global [%0], [%1], 16;" :: "r"(dst), "l"(src));
}
#define CP_COMMIT() asm volatile("cp.async.commit_group;" ::: "memory")
#define CP_WAIT(N)  asm volatile("cp.async.wait_group %0;" :: "n"(N) : "memory")

// ---------------- dtype detection + gstart seeding ------------------------------
__global__ void detect_kernel(const void* ei, const void* batch) {
    int t = threadIdx.x;  // 1024 threads
    if (t == 0) { g_ei_is64 = 1; g_b_is64 = 1; }
    if (t <= N_GRAPHS) g_gstart[t] = N_NODES;
    __syncthreads();
    long long v = ((const long long*)ei)[(long long)t * 312];
    if (v < 0 || v >= N_NODES) atomicExch(&g_ei_is64, 0);
    long long b = ((const long long*)batch)[t * 9];
    if (b < 0 || b >= N_GRAPHS) atomicExch(&g_b_is64, 0);
}

// ---------------- merged batch+edge conversion (g_cnt already zero) -------------
__global__ void convert_graph(const void* ei, const void* batch) {
    int i = blockIdx.x * blockDim.x + threadIdx.x;
    if (i < N_NODES) {
        int b = g_b_is64 ? (int)((const long long*)batch)[i] : ((const int*)batch)[i];
        b = min(max(b, 0), N_GRAPHS - 1);
        atomicMin(&g_gstart[b], i);
    }
    if (i >= N_EDGES) return;
    int s, d;
    if (g_ei_is64) {
        s = (int)((const long long*)ei)[i];
        d = (int)((const long long*)ei)[N_EDGES + i];
    } else {
        s = ((const int*)ei)[i];
        d = ((const int*)ei)[N_EDGES + i];
    }
    s = min(max(s, 0), N_NODES - 1);
    d = min(max(d, 0), N_NODES - 1);
    g_src32[i] = s;
    g_dst32[i] = d;
    atomicAdd(&g_cnt[d], 1);
}

// ---------------- fp32 -> bf16 hi/lo ---------------------------------------------
__global__ __launch_bounds__(256) void convert_in(const float4* __restrict__ src) {
    int i = blockIdx.x * 256 + threadIdx.x;
    if (i >= PAD_M * 64) return;
    int row = i >> 6;
    float4 v = make_float4(0.f, 0.f, 0.f, 0.f);
    if (row < N_NODES) v = src[i];
    __nv_bfloat162 h0 = __floats2bfloat162_rn(v.x, v.y);
    __nv_bfloat162 h1 = __floats2bfloat162_rn(v.z, v.w);
    float l0 = v.x - __low2float(h0);
    float l1 = v.y - __high2float(h0);
    float l2 = v.z - __low2float(h1);
    float l3 = v.w - __high2float(h1);
    ((__nv_bfloat162*)g_Ahi)[2 * i]     = h0;
    ((__nv_bfloat162*)g_Ahi)[2 * i + 1] = h1;
    ((__nv_bfloat162*)g_Alo)[2 * i]     = __floats2bfloat162_rn(l0, l1);
    ((__nv_bfloat162*)g_Alo)[2 * i + 1] = __floats2bfloat162_rn(l2, l3);
}

__global__ __launch_bounds__(256) void convert_w(const float* __restrict__ W1,
                                                 const float* __restrict__ W2,
                                                 const float* __restrict__ W3) {
    int i = blockIdx.x * 256 + threadIdx.x;
    if (i >= 3 * DIM * DIM) return;
    int w = i >> 16, r = i & 0xFFFF;
    int k = r >> 8, n = r & 255;
    const float* W = (w == 0) ? W1 : (w == 1) ? W2 : W3;
    float v = W[k * DIM + n];
    __nv_bfloat16 h = __float2bfloat16(v);
    __nv_bfloat16 l = __float2bfloat16(v - __bfloat162float(h));
    __nv_bfloat16* Be = g_Bext + w * KP * DIM;
    Be[k * DIM + n] = h;
    Be[(256 + k) * DIM + n] = l;
    Be[(512 + k) * DIM + n] = h;
}

// ---------------- WMMA GEMM: C[PAD_M,256] = [Ahi|Ahi|Alo] @ Bext ----------------
// BM=144, BN=256, BK=64, 12 chunks double-buffered via cp.async.
// 384 threads = 12 warps: 3(M) x 4(N), warp tile 48x64, acc 3x4.
// grid = 139 CTAs -> exactly one wave on 148 SMs.
#define GBM 144
#define GBN 256
#define GBK 64
#define NCHUNK (KP / GBK)         // 12
#define A_LD  (GBK + 8)           // 72
#define B_LD  (GBN + 8)           // 264
#define A_SZ  (GBM * A_LD * 2)    // 20736 B
#define B_SZ  (GBK * B_LD * 2)    // 33792 B
#define GEMM_SMEM (2 * (A_SZ + B_SZ))  // 109056 B
#define GEMM_THREADS 384

__global__ __launch_bounds__(GEMM_THREADS, 1) void gemm_wmma(int layer,
                                                             float* __restrict__ C) {
    extern __shared__ __align__(16) char smem[];
    const int tid = threadIdx.x;
    const int wid = tid >> 5;        // 0..11
    const int wm = wid % 3;          // 0..2 -> 48-row stripe
    const int wn = wid / 3;          // 0..3 -> 64-col stripe
    const int rowBase = blockIdx.x * GBM;
    const __nv_bfloat16* Bext = g_Bext + layer * KP * DIM;

    __nv_bfloat16* As[2] = {(__nv_bfloat16*)smem, (__nv_bfloat16*)(smem + A_SZ)};
    __nv_bfloat16* Bs[2] = {(__nv_bfloat16*)(smem + 2 * A_SZ),
                            (__nv_bfloat16*)(smem + 2 * A_SZ + B_SZ)};

    auto prefetch = [&](int c) {
        const int s = c & 1;
        const __nv_bfloat16* Ap = (c < 8) ? g_Ahi : g_Alo;
        const int ko = (c & 3) * GBK;
        uint32_t abase = (uint32_t)__cvta_generic_to_shared(As[s]);
        // A: 144 rows x 8 segs = 1152 tasks, 3 per thread
#pragma unroll
        for (int t = 0; t < 3; t++) {
            int q = tid + t * GEMM_THREADS;
            int row = q >> 3, seg = q & 7;
            cpa16(abase + (row * A_LD + seg * 8) * 2,
                  Ap + (rowBase + row) * DIM + ko + seg * 8);
        }
        uint32_t bbase = (uint32_t)__cvta_generic_to_shared(Bs[s]);
        // B: 64 rows x 32 segs = 2048 tasks
        for (int q = tid; q < 2048; q += GEMM_THREADS) {
            int row = q >> 5, seg = q & 31;
            cpa16(bbase + (row * B_LD + seg * 8) * 2,
                  Bext + (c * GBK + row) * DIM + seg * 8);
        }
        CP_COMMIT();
    };

    wmma::fragment<wmma::accumulator, 16, 16, 16, float> acc[3][4];
#pragma unroll
    for (int i = 0; i < 3; i++)
#pragma unroll
        for (int j = 0; j < 4; j++) wmma::fill_fragment(acc[i][j], 0.0f);

    prefetch(0);

    for (int c = 0; c < NCHUNK; c++) {
        const int s = c & 1;
        if (c + 1 < NCHUNK) {
            prefetch(c + 1);
            CP_WAIT(1);
        } else {
            CP_WAIT(0);
        }
        __syncthreads();
#pragma unroll
        for (int ks = 0; ks < GBK; ks += 16) {
            wmma::fragment<wmma::matrix_b, 16, 16, 16, __nv_bfloat16, wmma::row_major> bf[4];
#pragma unroll
            for (int j = 0; j < 4; j++)
                wmma::load_matrix_sync(bf[j], Bs[s] + ks * B_LD + wn * 64 + j * 16, B_LD);
#pragma unroll
            for (int i = 0; i < 3; i++) {
                wmma::fragment<wmma::matrix_a, 16, 16, 16, __nv_bfloat16, wmma::row_major> af;
                wmma::load_matrix_sync(af, As[s] + (wm * 48 + i * 16) * A_LD + ks, A_LD);
#pragma unroll
                for (int j = 0; j < 4; j++)
                    wmma::mma_sync(acc[i][j], af, bf[j], acc[i][j]);
            }
        }
        __syncthreads();
    }

#pragma unroll
    for (int i = 0; i < 3; i++)
#pragma unroll
        for (int j = 0; j < 4; j++)
            wmma::store_matrix_sync(
                &C[(rowBase + wm * 48 + i * 16) * DIM + wn * 64 + j * 16],
                acc[i][j], DIM, wmma::mem_row_major);
}

// ---------------- 3-phase scan ---------------------------------------------------
__global__ __launch_bounds__(SCAN_BLK) void scan_pre() {
    const int t = threadIdx.x;
    int i = blockIdx.x * SCAN_BLK + t;
    int v = (i < N_NODES) ? g_cnt[i] : 0;
#pragma unroll
    for (int o = 16; o; o >>= 1) v += __shfl_xor_sync(0xffffffffu, v, o);
    __shared__ int ws[8];
    if ((t & 31) == 0) ws[t >> 5] = v;
    __syncthreads();
    if (t < 8) {
        int s = ws[t];
#pragma unroll
        for (int o = 4; o; o >>= 1) s += __shfl_xor_sync(0xffu, s, o);
        if (t == 0) g_bsum[blockIdx.x] = s;
    }
}

__global__ void scan_mid() {
    const int t = threadIdx.x;  // 128
    __shared__ int s[128];
    int v = (t < N_SCANB) ? g_bsum[t] : 0;
    s[t] = v;
    __syncthreads();
    for (int o = 1; o < 128; o <<= 1) {
        int u = (t >= o) ? s[t - o] : 0;
        __syncthreads();
        s[t] += u;
        __syncthreads();
    }
    if (t < N_SCANB) g_bbase[t] = s[t] - v;
    if (t == 0) g_off[N_NODES] = s[N_SCANB - 1];
    if (t == 64) {
        g_gstart[N_GRAPHS] = N_NODES;
        for (int g = N_GRAPHS - 1; g >= 0; g--)
            g_gstart[g] = min(g_gstart[g], g_gstart[g + 1]);
    }
}

__global__ __launch_bounds__(SCAN_BLK) void scan_post() {
    const int t = threadIdx.x;
    int i = blockIdx.x * SCAN_BLK + t;
    int c = (i < N_NODES) ? g_cnt[i] : 0;
    int v = c;
#pragma unroll
    for (int o = 1; o < 32; o <<= 1) {
        int u = __shfl_up_sync(0xffffffffu, v, o);
        if ((t & 31) >= o) v += u;
    }
    __shared__ int ws[8];
    if ((t & 31) == 31) ws[t >> 5] = v;
    __syncthreads();
    if (t < 8) {
        int s = ws[t];
#pragma unroll
        for (int o = 1; o < 8; o <<= 1) {
            int u = __shfl_up_sync(0xffu, s, o);
            if (t >= o) s += u;
        }
        ws[t] = s;
    }
    __syncthreads();
    int warpBase = (t >= 32) ? ws[(t >> 5) - 1] : 0;
    int excl = g_bbase[blockIdx.x] + warpBase + v - c;
    if (i < N_NODES) {
        g_off[i] = excl;
        g_cur[i] = excl;
        g_dinv[i] = rsqrtf((float)c + 1.0f);
    }
}

// CSR fill + edge weight; also restores g_cnt = 0 for the next call
__global__ void fill_kernel() {
    int e = blockIdx.x * blockDim.x + threadIdx.x;
    if (e < N_NODES) g_cnt[e] = 0;   // scan_post was the last reader
    if (e < N_EDGES) {
        int s = g_src32[e];
        int d = g_dst32[e];
        int p = atomicAdd(&g_cur[d], 1);
        if (p >= 0 && p < N_EDGES) {
            g_csr[p] = s;
            g_w[p] = g_dinv[s] * g_dinv[d];
        }
    }
}

// ---------------- aggregation (+ fused bf16 hi/lo output for next GEMM) ---------
template <int MODE, int WRITE_BF>
__global__ __launch_bounds__(256) void agg_kernel(
    const float4* __restrict__ T4, const float4* __restrict__ bias4,
    const float4* __restrict__ resid4, float4* __restrict__ out4) {
    const int i = blockIdx.x;
    const int tid = threadIdx.x;
    const int d4 = tid & 63;
    const int eg = tid >> 6;
    const int e0 = g_off[i], e1 = g_off[i + 1];

    float4 a0 = make_float4(0.f, 0.f, 0.f, 0.f);
    float4 a1 = a0;
    int e = e0 + eg;
    for (; e + 4 < e1; e += 8) {
        int s0 = g_csr[e];
        float w0 = g_w[e];
        int s1 = g_csr[e + 4];
        float w1 = g_w[e + 4];
        float4 v0 = T4[s0 * 64 + d4];
        float4 v1 = T4[s1 * 64 + d4];
        a0.x = fmaf(w0, v0.x, a0.x); a0.y = fmaf(w0, v0.y, a0.y);
        a0.z = fmaf(w0, v0.z, a0.z); a0.w = fmaf(w0, v0.w, a0.w);
        a1.x = fmaf(w1, v1.x, a1.x); a1.y = fmaf(w1, v1.y, a1.y);
        a1.z = fmaf(w1, v1.z, a1.z); a1.w = fmaf(w1, v1.w, a1.w);
    }
    if (e < e1) {
        int s = g_csr[e];
        float w = g_w[e];
        float4 v = T4[s * 64 + d4];
        a0.x = fmaf(w, v.x, a0.x); a0.y = fmaf(w, v.y, a0.y);
        a0.z = fmaf(w, v.z, a0.z); a0.w = fmaf(w, v.w, a0.w);
    }
    a0.x += a1.x; a0.y += a1.y; a0.z += a1.z; a0.w += a1.w;

    __shared__ float4 part[3][64];
    if (eg > 0) part[eg - 1][d4] = a0;
    __syncthreads();
    if (eg == 0) {
        const float di = g_dinv[i];
        float4 self = T4[i * 64 + d4];
        float dii = di * di;
        float4 b = bias4[d4];
        float4 acc;
        acc.x = a0.x + part[0][d4].x + part[1][d4].x + part[2][d4].x + self.x * dii + b.x;
        acc.y = a0.y + part[0][d4].y + part[1][d4].y + part[2][d4].y + self.y * dii + b.y;
        acc.z = a0.z + part[0][d4].z + part[1][d4].z + part[2][d4].z + self.z * dii + b.z;
        acc.w = a0.w + part[0][d4].w + part[1][d4].w + part[2][d4].w + self.w * dii + b.w;
        if (MODE == 1) {
            float4 r = resid4[i * 64 + d4];
            acc.x += r.x; acc.y += r.y; acc.z += r.z; acc.w += r.w;
        }
        if (MODE <= 1) {
            acc.x = fmaxf(acc.x, 0.f); acc.y = fmaxf(acc.y, 0.f);
            acc.z = fmaxf(acc.z, 0.f); acc.w = fmaxf(acc.w, 0.f);
        }
        out4[i * 64 + d4] = acc;
        if (WRITE_BF) {
            __nv_bfloat162 h0 = __floats2bfloat162_rn(acc.x, acc.y);
            __nv_bfloat162 h1 = __floats2bfloat162_rn(acc.z, acc.w);
            float l0 = acc.x - __low2float(h0);
            float l1 = acc.y - __high2float(h0);
            float l2 = acc.z - __low2float(h1);
            float l3 = acc.w - __high2float(h1);
            int base = i * 128 + d4 * 2;
            ((__nv_bfloat162*)g_Ahi)[base]     = h0;
            ((__nv_bfloat162*)g_Ahi)[base + 1] = h1;
            ((__nv_bfloat162*)g_Alo)[base]     = __floats2bfloat162_rn(l0, l1);
            ((__nv_bfloat162*)g_Alo)[base + 1] = __floats2bfloat162_rn(l2, l3);
        }
    }
}

// ---------------- merged pooling + classifier + log_softmax ----------------------
__global__ __launch_bounds__(256) void pool_cls(const float4* __restrict__ h4,
                                                const float* __restrict__ Wc,
                                                const float* __restrict__ bc,
                                                float* __restrict__ out,
                                                int out_size) {
    const int g = blockIdx.x;
    const int tid = threadIdx.x;
    const int d4 = tid & 63;
    const int rg = tid >> 6;
    const int r0 = g_gstart[g], r1 = g_gstart[g + 1];
    float4 acc = make_float4(0.f, 0.f, 0.f, 0.f);
    for (int i = r0 + rg; i < r1; i += 4) {
        float4 v = h4[i * 64 + d4];
        acc.x += v.x; acc.y += v.y; acc.z += v.z; acc.w += v.w;
    }
    __shared__ float4 part[4][64];
    __shared__ float p[DIM];
    __shared__ float logits[N_CLASSES];
    part[rg][d4] = acc;
    __syncthreads();
    if (rg == 0) {
        float inv = 1.0f / fmaxf((float)(r1 - r0), 1.0f);
        p[d4 * 4 + 0] = (part[0][d4].x + part[1][d4].x + part[2][d4].x + part[3][d4].x) * inv;
        p[d4 * 4 + 1] = (part[0][d4].y + part[1][d4].y + part[2][d4].y + part[3][d4].y) * inv;
        p[d4 * 4 + 2] = (part[0][d4].z + part[1][d4].z + part[2][d4].z + part[3][d4].z) * inv;
        p[d4 * 4 + 3] = (part[0][d4].w + part[1][d4].w + part[2][d4].w + part[3][d4].w) * inv;
    }
    __syncthreads();
    const int w = tid >> 5, lane = tid & 31;
    for (int cls = w; cls < N_CLASSES; cls += 8) {
        float s = 0.0f;
        for (int k = lane; k < DIM; k += 32) s += p[k] * Wc[k * N_CLASSES + cls];
#pragma unroll
        for (int o = 16; o; o >>= 1) s += __shfl_xor_sync(0xffffffffu, s, o);
        if (lane == 0) logits[cls] = s + bc[cls];
    }
    __syncthreads();
    if (tid < N_CLASSES) {
        float mx = -1e30f;
#pragma unroll
        for (int k = 0; k < N_CLASSES; k++) mx = fmaxf(mx, logits[k]);
        float sum = 0.0f;
#pragma unroll
        for (int k = 0; k < N_CLASSES; k++) sum += expf(logits[k] - mx);
        float lse = mx + logf(sum);
        out[g * N_CLASSES + tid] = logits[tid];
        if (out_size >= 2 * N_GRAPHS * N_CLASSES)
            out[N_GRAPHS * N_CLASSES + g * N_CLASSES + tid] = logits[tid] - lse;
    }
}

// ---------------- launch ----------------------------------------------------------
extern "C" void kernel_launch(void* const* d_in, const int* in_sizes, int n_in,
                              void* d_out, int out_size) {
    const float* x = (const float*)d_in[0];
    const void*  ei = d_in[1];
    const void*  batch = d_in[2];
    const float* W1 = (const float*)d_in[3];
    const float* b1 = (const float*)d_in[4];
    const float* W2 = (const float*)d_in[5];
    const float* b2 = (const float*)d_in[6];
    const float* W3 = (const float*)d_in[7];
    const float* b3 = (const float*)d_in[8];
    const float* Wc = (const float*)d_in[9];
    const float* bc = (const float*)d_in[10];
    float* out = (float*)d_out;

    float* T; float* A; float* B;
    cudaGetSymbolAddress((void**)&T, g_T);
    cudaGetSymbolAddress((void**)&A, g_A);
    cudaGetSymbolAddress((void**)&B, g_B);

    static int smem_set = 0;
    if (!smem_set) {
        cudaFuncSetAttribute(gemm_wmma, cudaFuncAttributeMaxDynamicSharedMemorySize,
                             GEMM_SMEM);
        smem_set = 1;
    }

    const int CONV_GRID = (PAD_M * 64 + 255) / 256;
    const int EDGE_GRID = (N_EDGES + 255) / 256;
    const int ggrid = PAD_M / GBM;  // 139

    const bool use_side = (g_side != nullptr && g_evf != nullptr && g_evj != nullptr);

    // head: dtype detect (needed by side chain)
    detect_kernel<<<1, 1024>>>(ei, batch);

    if (use_side) {
        cudaEventRecord(g_evf, 0);
        cudaStreamWaitEvent(g_side, g_evf, 0);
        // side stream: graph preprocessing (hidden under converts + gemm1)
        convert_graph<<<EDGE_GRID, 256, 0, g_side>>>(ei, batch);
        scan_pre<<<N_SCANB, SCAN_BLK, 0, g_side>>>();
        scan_mid<<<1, 128, 0, g_side>>>();
        scan_post<<<N_SCANB, SCAN_BLK, 0, g_side>>>();
        fill_kernel<<<EDGE_GRID, 256, 0, g_side>>>();
        cudaEventRecord(g_evj, g_side);
    } else {
        convert_graph<<<EDGE_GRID, 256>>>(ei, batch);
        scan_pre<<<N_SCANB, SCAN_BLK>>>();
        scan_mid<<<1, 128>>>();
        scan_post<<<N_SCANB, SCAN_BLK>>>();
        fill_kernel<<<EDGE_GRID, 256>>>();
    }

    // main stream: converts + layer-1 GEMM
    convert_in<<<CONV_GRID, 256>>>((const float4*)x);
    convert_w<<<(3 * DIM * DIM + 255) / 256, 256>>>(W1, W2, W3);
    gemm_wmma<<<ggrid, GEMM_THREADS, GEMM_SMEM>>>(0, T);

    if (use_side) cudaStreamWaitEvent(0, g_evj, 0);   // join before agg1

    // layer 1 aggregate (writes bf16 hi/lo for layer-2 GEMM)
    agg_kernel<0, 1><<<N_NODES, 256>>>((const float4*)T, (const float4*)b1, nullptr,
                                       (float4*)A);
    // layer 2
    gemm_wmma<<<ggrid, GEMM_THREADS, GEMM_SMEM>>>(1, T);
    agg_kernel<1, 1><<<N_NODES, 256>>>((const float4*)T, (const float4*)b2,
                                       (const float4*)A, (float4*)B);
    // layer 3
    gemm_wmma<<<ggrid, GEMM_THREADS, GEMM_SMEM>>>(2, T);
    agg_kernel<2, 0><<<N_NODES, 256>>>((const float4*)T, (const float4*)b3, nullptr,
                                       (float4*)A);

    // merged pooling + classifier
    pool_cls<<<N_GRAPHS, 256>>>((const float4*)A, Wc, bc, out, out_size);
}

// round 11
// speedup vs baseline: 2.0712x; 1.0573x over previous
#include <cuda_runtime.h>
#include <cuda_bf16.h>
#include <mma.h>
#include <math.h>
#include <stdint.h>

using namespace nvcuda;

// ---------------------------------------------------------------------------
// GCN_9062380994846: 3-layer GCN + mean pool + classifier + log_softmax
// GEMM1/2: WMMA bf16 hi/lo split (K'=768), single-wave grid (139 CTAs).
// Layer 3 collapsed algebraically: logits = (mean_g agg(h2)) @ (W3@Wc) + b3@Wc + bc
// ---------------------------------------------------------------------------

#define N_NODES   20000
#define N_EDGES   320000
#define DIM       256
#define N_GRAPHS  64
#define N_CLASSES 10
#define SCAN_BLK  256
#define N_SCANB   ((N_NODES + SCAN_BLK - 1) / SCAN_BLK)   // 79
#define PAD_M     20016                                    // 139 * 144
#define KP        768

// ---------------- scratch ----------------------------------------------------
__device__ float g_T[PAD_M * DIM];
__device__ float g_A[PAD_M * DIM];
__device__ float g_B[PAD_M * DIM];
__device__ __nv_bfloat16 g_Ahi[PAD_M * DIM];
__device__ __nv_bfloat16 g_Alo[PAD_M * DIM];
__device__ __nv_bfloat16 g_Bext[2 * KP * DIM];   // layers 1-2 only
__device__ float g_W3Wc[DIM * N_CLASSES];
__device__ float g_bWc[N_CLASSES];
__device__ int   g_src32[N_EDGES];
__device__ int   g_dst32[N_EDGES];
__device__ int   g_cnt[N_NODES];        // zero-init at load; restored by fill_kernel
__device__ int   g_off[N_NODES + 1];
__device__ int   g_cur[N_NODES];
__device__ int   g_csr[N_EDGES];
__device__ float g_w[N_EDGES];
__device__ float g_dinv[N_NODES];
__device__ int   g_bsum[N_SCANB];
__device__ int   g_bbase[N_SCANB];
__device__ int   g_gstart[N_GRAPHS + 1];
__device__ float g_pool[N_GRAPHS * DIM];
__device__ int   g_ei_is64;
__device__ int   g_b_is64;

// ---------------- host-side aux (created at static init, reused forever) ------
static cudaStream_t g_side = nullptr;
static cudaEvent_t  g_evf = nullptr, g_evj = nullptr;
struct AuxInit {
    AuxInit() {
        cudaStreamCreateWithFlags(&g_side, cudaStreamNonBlocking);
        cudaEventCreateWithFlags(&g_evf, cudaEventDisableTiming);
        cudaEventCreateWithFlags(&g_evj, cudaEventDisableTiming);
    }
};
static AuxInit g_auxinit;

// ---------------- cp.async helpers ---------------------------------------------
__device__ __forceinline__ void cpa16(uint32_t dst, const void* src) {
    asm volatile("cp.async.cg.shared.global [%0], [%1], 16;" :: "r"(dst), "l"(src));
}
#define CP_COMMIT() asm volatile("cp.async.commit_group;" ::: "memory")
#define CP_WAIT(N)  asm volatile("cp.async.wait_group %0;" :: "n"(N) : "memory")

// ---------------- dtype detection + init ----------------------------------------
__global__ void detect_kernel(const void* ei, const void* batch) {
    int t = threadIdx.x;  // 1024 threads
    if (t == 0) { g_ei_is64 = 1; g_b_is64 = 1; }
    if (t <= N_GRAPHS) g_gstart[t] = N_NODES;
    for (int i = t; i < N_GRAPHS * DIM; i += 1024) g_pool[i] = 0.0f;
    __syncthreads();
    long long v = ((const long long*)ei)[(long long)t * 312];
    if (v < 0 || v >= N_NODES) atomicExch(&g_ei_is64, 0);
    long long b = ((const long long*)batch)[t * 9];
    if (b < 0 || b >= N_GRAPHS) atomicExch(&g_b_is64, 0);
}

// ---------------- merged batch+edge conversion (g_cnt already zero) -------------
__global__ void convert_graph(const void* ei, const void* batch) {
    int i = blockIdx.x * blockDim.x + threadIdx.x;
    if (i < N_NODES) {
        int b = g_b_is64 ? (int)((const long long*)batch)[i] : ((const int*)batch)[i];
        b = min(max(b, 0), N_GRAPHS - 1);
        atomicMin(&g_gstart[b], i);
    }
    if (i >= N_EDGES) return;
    int s, d;
    if (g_ei_is64) {
        s = (int)((const long long*)ei)[i];
        d = (int)((const long long*)ei)[N_EDGES + i];
    } else {
        s = ((const int*)ei)[i];
        d = ((const int*)ei)[N_EDGES + i];
    }
    s = min(max(s, 0), N_NODES - 1);
    d = min(max(d, 0), N_NODES - 1);
    g_src32[i] = s;
    g_dst32[i] = d;
    atomicAdd(&g_cnt[d], 1);
}

// ---------------- fp32 -> bf16 hi/lo ---------------------------------------------
__global__ __launch_bounds__(256) void convert_in(const float4* __restrict__ src) {
    int i = blockIdx.x * 256 + threadIdx.x;
    if (i >= PAD_M * 64) return;
    int row = i >> 6;
    float4 v = make_float4(0.f, 0.f, 0.f, 0.f);
    if (row < N_NODES) v = src[i];
    __nv_bfloat162 h0 = __floats2bfloat162_rn(v.x, v.y);
    __nv_bfloat162 h1 = __floats2bfloat162_rn(v.z, v.w);
    float l0 = v.x - __low2float(h0);
    float l1 = v.y - __high2float(h0);
    float l2 = v.z - __low2float(h1);
    float l3 = v.w - __high2float(h1);
    ((__nv_bfloat162*)g_Ahi)[2 * i]     = h0;
    ((__nv_bfloat162*)g_Ahi)[2 * i + 1] = h1;
    ((__nv_bfloat162*)g_Alo)[2 * i]     = __floats2bfloat162_rn(l0, l1);
    ((__nv_bfloat162*)g_Alo)[2 * i + 1] = __floats2bfloat162_rn(l2, l3);
}

// weights for layers 1-2 only (layer 3 folded into W3Wc)
__global__ __launch_bounds__(256) void convert_w(const float* __restrict__ W1,
                                                 const float* __restrict__ W2) {
    int i = blockIdx.x * 256 + threadIdx.x;
    if (i >= 2 * DIM * DIM) return;
    int w = i >> 16, r = i & 0xFFFF;
    int k = r >> 8, n = r & 255;
    const float* W = (w == 0) ? W1 : W2;
    float v = W[k * DIM + n];
    __nv_bfloat16 h = __float2bfloat16(v);
    __nv_bfloat16 l = __float2bfloat16(v - __bfloat162float(h));
    __nv_bfloat16* Be = g_Bext + w * KP * DIM;
    Be[k * DIM + n] = h;
    Be[(256 + k) * DIM + n] = l;
    Be[(512 + k) * DIM + n] = h;
}

// W3Wc = W3 @ Wc (fp32 exact), bWc = b3 @ Wc + bc
__global__ __launch_bounds__(256) void w3wc_kernel(const float* __restrict__ W3,
                                                   const float* __restrict__ Wc,
                                                   const float* __restrict__ b3,
                                                   const float* __restrict__ bc) {
    int idx = blockIdx.x * 256 + threadIdx.x;
    if (idx < DIM * N_CLASSES) {
        int k = idx / N_CLASSES, c = idx % N_CLASSES;
        float s = 0.0f;
        for (int m = 0; m < DIM; m++) s += W3[k * DIM + m] * Wc[m * N_CLASSES + c];
        g_W3Wc[idx] = s;
    }
    if (idx < N_CLASSES) {
        float s = 0.0f;
        for (int k = 0; k < DIM; k++) s += b3[k] * Wc[k * N_CLASSES + idx];
        g_bWc[idx] = s + bc[idx];
    }
}

// ---------------- WMMA GEMM: C[PAD_M,256] = [Ahi|Ahi|Alo] @ Bext ----------------
#define GBM 144
#define GBN 256
#define GBK 64
#define NCHUNK (KP / GBK)         // 12
#define A_LD  (GBK + 8)
#define B_LD  (GBN + 8)
#define A_SZ  (GBM * A_LD * 2)
#define B_SZ  (GBK * B_LD * 2)
#define GEMM_SMEM (2 * (A_SZ + B_SZ))
#define GEMM_THREADS 384

__global__ __launch_bounds__(GEMM_THREADS, 1) void gemm_wmma(int layer,
                                                             float* __restrict__ C) {
    extern __shared__ __align__(16) char smem[];
    const int tid = threadIdx.x;
    const int wid = tid >> 5;
    const int wm = wid % 3;
    const int wn = wid / 3;
    const int rowBase = blockIdx.x * GBM;
    const __nv_bfloat16* Bext = g_Bext + layer * KP * DIM;

    __nv_bfloat16* As[2] = {(__nv_bfloat16*)smem, (__nv_bfloat16*)(smem + A_SZ)};
    __nv_bfloat16* Bs[2] = {(__nv_bfloat16*)(smem + 2 * A_SZ),
                            (__nv_bfloat16*)(smem + 2 * A_SZ + B_SZ)};

    auto prefetch = [&](int c) {
        const int s = c & 1;
        const __nv_bfloat16* Ap = (c < 8) ? g_Ahi : g_Alo;
        const int ko = (c & 3) * GBK;
        uint32_t abase = (uint32_t)__cvta_generic_to_shared(As[s]);
#pragma unroll
        for (int t = 0; t < 3; t++) {
            int q = tid + t * GEMM_THREADS;
            int row = q >> 3, seg = q & 7;
            cpa16(abase + (row * A_LD + seg * 8) * 2,
                  Ap + (rowBase + row) * DIM + ko + seg * 8);
        }
        uint32_t bbase = (uint32_t)__cvta_generic_to_shared(Bs[s]);
        for (int q = tid; q < 2048; q += GEMM_THREADS) {
            int row = q >> 5, seg = q & 31;
            cpa16(bbase + (row * B_LD + seg * 8) * 2,
                  Bext + (c * GBK + row) * DIM + seg * 8);
        }
        CP_COMMIT();
    };

    wmma::fragment<wmma::accumulator, 16, 16, 16, float> acc[3][4];
#pragma unroll
    for (int i = 0; i < 3; i++)
#pragma unroll
        for (int j = 0; j < 4; j++) wmma::fill_fragment(acc[i][j], 0.0f);

    prefetch(0);

    for (int c = 0; c < NCHUNK; c++) {
        const int s = c & 1;
        if (c + 1 < NCHUNK) {
            prefetch(c + 1);
            CP_WAIT(1);
        } else {
            CP_WAIT(0);
        }
        __syncthreads();
#pragma unroll
        for (int ks = 0; ks < GBK; ks += 16) {
            wmma::fragment<wmma::matrix_b, 16, 16, 16, __nv_bfloat16, wmma::row_major> bf[4];
#pragma unroll
            for (int j = 0; j < 4; j++)
                wmma::load_matrix_sync(bf[j], Bs[s] + ks * B_LD + wn * 64 + j * 16, B_LD);
#pragma unroll
            for (int i = 0; i < 3; i++) {
                wmma::fragment<wmma::matrix_a, 16, 16, 16, __nv_bfloat16, wmma::row_major> af;
                wmma::load_matrix_sync(af, As[s] + (wm * 48 + i * 16) * A_LD + ks, A_LD);
#pragma unroll
                for (int j = 0; j < 4; j++)
                    wmma::mma_sync(acc[i][j], af, bf[j], acc[i][j]);
            }
        }
        __syncthreads();
    }

#pragma unroll
    for (int i = 0; i < 3; i++)
#pragma unroll
        for (int j = 0; j < 4; j++)
            wmma::store_matrix_sync(
                &C[(rowBase + wm * 48 + i * 16) * DIM + wn * 64 + j * 16],
                acc[i][j], DIM, wmma::mem_row_major);
}

// ---------------- 3-phase scan ---------------------------------------------------
__global__ __launch_bounds__(SCAN_BLK) void scan_pre() {
    const int t = threadIdx.x;
    int i = blockIdx.x * SCAN_BLK + t;
    int v = (i < N_NODES) ? g_cnt[i] : 0;
#pragma unroll
    for (int o = 16; o; o >>= 1) v += __shfl_xor_sync(0xffffffffu, v, o);
    __shared__ int ws[8];
    if ((t & 31) == 0) ws[t >> 5] = v;
    __syncthreads();
    if (t < 8) {
        int s = ws[t];
#pragma unroll
        for (int o = 4; o; o >>= 1) s += __shfl_xor_sync(0xffu, s, o);
        if (t == 0) g_bsum[blockIdx.x] = s;
    }
}

__global__ void scan_mid() {
    const int t = threadIdx.x;  // 128
    __shared__ int s[128];
    int v = (t < N_SCANB) ? g_bsum[t] : 0;
    s[t] = v;
    __syncthreads();
    for (int o = 1; o < 128; o <<= 1) {
        int u = (t >= o) ? s[t - o] : 0;
        __syncthreads();
        s[t] += u;
        __syncthreads();
    }
    if (t < N_SCANB) g_bbase[t] = s[t] - v;
    if (t == 0) g_off[N_NODES] = s[N_SCANB - 1];
    if (t == 64) {
        g_gstart[N_GRAPHS] = N_NODES;
        for (int g = N_GRAPHS - 1; g >= 0; g--)
            g_gstart[g] = min(g_gstart[g], g_gstart[g + 1]);
    }
}

__global__ __launch_bounds__(SCAN_BLK) void scan_post() {
    const int t = threadIdx.x;
    int i = blockIdx.x * SCAN_BLK + t;
    int c = (i < N_NODES) ? g_cnt[i] : 0;
    int v = c;
#pragma unroll
    for (int o = 1; o < 32; o <<= 1) {
        int u = __shfl_up_sync(0xffffffffu, v, o);
        if ((t & 31) >= o) v += u;
    }
    __shared__ int ws[8];
    if ((t & 31) == 31) ws[t >> 5] = v;
    __syncthreads();
    if (t < 8) {
        int s = ws[t];
#pragma unroll
        for (int o = 1; o < 8; o <<= 1) {
            int u = __shfl_up_sync(0xffu, s, o);
            if (t >= o) s += u;
        }
        ws[t] = s;
    }
    __syncthreads();
    int warpBase = (t >= 32) ? ws[(t >> 5) - 1] : 0;
    int excl = g_bbase[blockIdx.x] + warpBase + v - c;
    if (i < N_NODES) {
        g_off[i] = excl;
        g_cur[i] = excl;
        g_dinv[i] = rsqrtf((float)c + 1.0f);
    }
}

// CSR fill + edge weight; also restores g_cnt = 0 for the next call
__global__ void fill_kernel() {
    int e = blockIdx.x * blockDim.x + threadIdx.x;
    if (e < N_NODES) g_cnt[e] = 0;
    if (e < N_EDGES) {
        int s = g_src32[e];
        int d = g_dst32[e];
        int p = atomicAdd(&g_cur[d], 1);
        if (p >= 0 && p < N_EDGES) {
            g_csr[p] = s;
            g_w[p] = g_dinv[s] * g_dinv[d];
        }
    }
}

// ---------------- aggregation (+ fused bf16 hi/lo output for next GEMM) ---------
template <int MODE, int WRITE_BF>
__global__ __launch_bounds__(256) void agg_kernel(
    const float4* __restrict__ T4, const float4* __restrict__ bias4,
    const float4* __restrict__ resid4, float4* __restrict__ out4) {
    const int i = blockIdx.x;
    const int tid = threadIdx.x;
    const int d4 = tid & 63;
    const int eg = tid >> 6;
    const int e0 = g_off[i], e1 = g_off[i + 1];

    float4 a0 = make_float4(0.f, 0.f, 0.f, 0.f);
    float4 a1 = a0;
    int e = e0 + eg;
    for (; e + 4 < e1; e += 8) {
        int s0 = g_csr[e];
        float w0 = g_w[e];
        int s1 = g_csr[e + 4];
        float w1 = g_w[e + 4];
        float4 v0 = T4[s0 * 64 + d4];
        float4 v1 = T4[s1 * 64 + d4];
        a0.x = fmaf(w0, v0.x, a0.x); a0.y = fmaf(w0, v0.y, a0.y);
        a0.z = fmaf(w0, v0.z, a0.z); a0.w = fmaf(w0, v0.w, a0.w);
        a1.x = fmaf(w1, v1.x, a1.x); a1.y = fmaf(w1, v1.y, a1.y);
        a1.z = fmaf(w1, v1.z, a1.z); a1.w = fmaf(w1, v1.w, a1.w);
    }
    if (e < e1) {
        int s = g_csr[e];
        float w = g_w[e];
        float4 v = T4[s * 64 + d4];
        a0.x = fmaf(w, v.x, a0.x); a0.y = fmaf(w, v.y, a0.y);
        a0.z = fmaf(w, v.z, a0.z); a0.w = fmaf(w, v.w, a0.w);
    }
    a0.x += a1.x; a0.y += a1.y; a0.z += a1.z; a0.w += a1.w;

    __shared__ float4 part[3][64];
    if (eg > 0) part[eg - 1][d4] = a0;
    __syncthreads();
    if (eg == 0) {
        const float di = g_dinv[i];
        float4 self = T4[i * 64 + d4];
        float dii = di * di;
        float4 b = bias4[d4];
        float4 acc;
        acc.x = a0.x + part[0][d4].x + part[1][d4].x + part[2][d4].x + self.x * dii + b.x;
        acc.y = a0.y + part[0][d4].y + part[1][d4].y + part[2][d4].y + self.y * dii + b.y;
        acc.z = a0.z + part[0][d4].z + part[1][d4].z + part[2][d4].z + self.z * dii + b.z;
        acc.w = a0.w + part[0][d4].w + part[1][d4].w + part[2][d4].w + self.w * dii + b.w;
        if (MODE == 1) {
            float4 r = resid4[i * 64 + d4];
            acc.x += r.x; acc.y += r.y; acc.z += r.z; acc.w += r.w;
        }
        if (MODE <= 1) {
            acc.x = fmaxf(acc.x, 0.f); acc.y = fmaxf(acc.y, 0.f);
            acc.z = fmaxf(acc.z, 0.f); acc.w = fmaxf(acc.w, 0.f);
        }
        out4[i * 64 + d4] = acc;
        if (WRITE_BF) {
            __nv_bfloat162 h0 = __floats2bfloat162_rn(acc.x, acc.y);
            __nv_bfloat162 h1 = __floats2bfloat162_rn(acc.z, acc.w);
            float l0 = acc.x - __low2float(h0);
            float l1 = acc.y - __high2float(h0);
            float l2 = acc.z - __low2float(h1);
            float l3 = acc.w - __high2float(h1);
            int base = i * 128 + d4 * 2;
            ((__nv_bfloat162*)g_Ahi)[base]     = h0;
            ((__nv_bfloat162*)g_Ahi)[base + 1] = h1;
            ((__nv_bfloat162*)g_Alo)[base]     = __floats2bfloat162_rn(l0, l1);
            ((__nv_bfloat162*)g_Alo)[base + 1] = __floats2bfloat162_rn(l2, l3);
        }
    }
}

// ---------------- graph_reduce: s_g = sum_{i in g} [dinv_i^2 h2_i + sum_e w_e h2_src]
// grid = 64 graphs x 16 slices; 256 threads = 64 float4 lanes x 4 subgroups.
__global__ __launch_bounds__(256) void graph_reduce(const float4* __restrict__ h4) {
    const int g = blockIdx.x >> 4;
    const int slice = blockIdx.x & 15;
    const int tid = threadIdx.x;
    const int d4 = tid & 63;
    const int eg = tid >> 6;
    const int sub = slice * 4 + eg;       // 0..63
    const int r0 = g_gstart[g], r1 = g_gstart[g + 1];

    float4 acc = make_float4(0.f, 0.f, 0.f, 0.f);
    for (int i = r0 + sub; i < r1; i += 64) {
        float di = g_dinv[i];
        float w = di * di;
        float4 v = h4[i * 64 + d4];
        acc.x = fmaf(w, v.x, acc.x); acc.y = fmaf(w, v.y, acc.y);
        acc.z = fmaf(w, v.z, acc.z); acc.w = fmaf(w, v.w, acc.w);
        const int e0 = g_off[i], e1 = g_off[i + 1];
        for (int e = e0; e < e1; e++) {
            int s = g_csr[e];
            float we = g_w[e];
            float4 u = h4[s * 64 + d4];
            acc.x = fmaf(we, u.x, acc.x); acc.y = fmaf(we, u.y, acc.y);
            acc.z = fmaf(we, u.z, acc.z); acc.w = fmaf(we, u.w, acc.w);
        }
    }
    __shared__ float4 part[4][64];
    part[eg][d4] = acc;
    __syncthreads();
    if (eg == 0) {
        float4 t;
        t.x = part[0][d4].x + part[1][d4].x + part[2][d4].x + part[3][d4].x;
        t.y = part[0][d4].y + part[1][d4].y + part[2][d4].y + part[3][d4].y;
        t.z = part[0][d4].z + part[1][d4].z + part[2][d4].z + part[3][d4].z;
        t.w = part[0][d4].w + part[1][d4].w + part[2][d4].w + part[3][d4].w;
        float* dst = g_pool + g * DIM + d4 * 4;
        atomicAdd(dst + 0, t.x);
        atomicAdd(dst + 1, t.y);
        atomicAdd(dst + 2, t.z);
        atomicAdd(dst + 3, t.w);
    }
}

// ---------------- classifier: logits = (s/n) @ W3Wc + bWc; log_softmax ----------
__global__ __launch_bounds__(256) void cls_kernel(float* __restrict__ out,
                                                  int out_size) {
    const int g = blockIdx.x;
    const int t = threadIdx.x;
    __shared__ float p[DIM];
    __shared__ float logits[N_CLASSES];
    int n = g_gstart[g + 1] - g_gstart[g];
    float inv = 1.0f / fmaxf((float)n, 1.0f);
    p[t] = g_pool[g * DIM + t] * inv;
    __syncthreads();
    const int w = t >> 5, lane = t & 31;
    for (int cls = w; cls < N_CLASSES; cls += 8) {
        float s = 0.0f;
        for (int k = lane; k < DIM; k += 32) s += p[k] * g_W3Wc[k * N_CLASSES + cls];
#pragma unroll
        for (int o = 16; o; o >>= 1) s += __shfl_xor_sync(0xffffffffu, s, o);
        if (lane == 0) logits[cls] = s + g_bWc[cls];
    }
    __syncthreads();
    if (t < N_CLASSES) {
        float mx = -1e30f;
#pragma unroll
        for (int k = 0; k < N_CLASSES; k++) mx = fmaxf(mx, logits[k]);
        float sum = 0.0f;
#pragma unroll
        for (int k = 0; k < N_CLASSES; k++) sum += expf(logits[k] - mx);
        float lse = mx + logf(sum);
        out[g * N_CLASSES + t] = logits[t];
        if (out_size >= 2 * N_GRAPHS * N_CLASSES)
            out[N_GRAPHS * N_CLASSES + g * N_CLASSES + t] = logits[t] - lse;
    }
}

// ---------------- launch ----------------------------------------------------------
extern "C" void kernel_launch(void* const* d_in, const int* in_sizes, int n_in,
                              void* d_out, int out_size) {
    const float* x = (const float*)d_in[0];
    const void*  ei = d_in[1];
    const void*  batch = d_in[2];
    const float* W1 = (const float*)d_in[3];
    const float* b1 = (const float*)d_in[4];
    const float* W2 = (const float*)d_in[5];
    const float* b2 = (const float*)d_in[6];
    const float* W3 = (const float*)d_in[7];
    const float* b3 = (const float*)d_in[8];
    const float* Wc = (const float*)d_in[9];
    const float* bc = (const float*)d_in[10];
    float* out = (float*)d_out;

    float* T; float* A; float* B;
    cudaGetSymbolAddress((void**)&T, g_T);
    cudaGetSymbolAddress((void**)&A, g_A);
    cudaGetSymbolAddress((void**)&B, g_B);

    static int smem_set = 0;
    if (!smem_set) {
        cudaFuncSetAttribute(gemm_wmma, cudaFuncAttributeMaxDynamicSharedMemorySize,
                             GEMM_SMEM);
        smem_set = 1;
    }

    const int CONV_GRID = (PAD_M * 64 + 255) / 256;
    const int EDGE_GRID = (N_EDGES + 255) / 256;
    const int ggrid = PAD_M / GBM;  // 139

    const bool use_side = (g_side != nullptr && g_evf != nullptr && g_evj != nullptr);

    // head: dtype detect + zero pool + seed gstart
    detect_kernel<<<1, 1024>>>(ei, batch);

    if (use_side) {
        cudaEventRecord(g_evf, 0);
        cudaStreamWaitEvent(g_side, g_evf, 0);
        convert_graph<<<EDGE_GRID, 256, 0, g_side>>>(ei, batch);
        scan_pre<<<N_SCANB, SCAN_BLK, 0, g_side>>>();
        scan_mid<<<1, 128, 0, g_side>>>();
        scan_post<<<N_SCANB, SCAN_BLK, 0, g_side>>>();
        fill_kernel<<<EDGE_GRID, 256, 0, g_side>>>();
        w3wc_kernel<<<10, 256, 0, g_side>>>(W3, Wc, b3, bc);
        cudaEventRecord(g_evj, g_side);
    } else {
        convert_graph<<<EDGE_GRID, 256>>>(ei, batch);
        scan_pre<<<N_SCANB, SCAN_BLK>>>();
        scan_mid<<<1, 128>>>();
        scan_post<<<N_SCANB, SCAN_BLK>>>();
        fill_kernel<<<EDGE_GRID, 256>>>();
        w3wc_kernel<<<10, 256>>>(W3, Wc, b3, bc);
    }

    // main stream: converts + layer-1 GEMM
    convert_in<<<CONV_GRID, 256>>>((const float4*)x);
    convert_w<<<(2 * DIM * DIM + 255) / 256, 256>>>(W1, W2);
    gemm_wmma<<<ggrid, GEMM_THREADS, GEMM_SMEM>>>(0, T);

    if (use_side) cudaStreamWaitEvent(0, g_evj, 0);   // join before agg1

    // layer 1 aggregate (writes bf16 hi/lo for layer-2 GEMM)
    agg_kernel<0, 1><<<N_NODES, 256>>>((const float4*)T, (const float4*)b1, nullptr,
                                       (float4*)A);
    // layer 2 (h2 fp32 only — layer 3 consumed algebraically)
    gemm_wmma<<<ggrid, GEMM_THREADS, GEMM_SMEM>>>(1, T);
    agg_kernel<1, 0><<<N_NODES, 256>>>((const float4*)T, (const float4*)b2,
                                       (const float4*)A, (float4*)B);
    // collapsed layer 3 + pooling + classifier
    graph_reduce<<<N_GRAPHS * 16, 256>>>((const float4*)B);
    cls_kernel<<<N_GRAPHS, 256>>>(out, out_size);
}